// round 14
// baseline (speedup 1.0000x reference)
#include <cuda_runtime.h>
#include <cuda_bf16.h>
#include <math.h>
#include <stdint.h>

// Problem constants
constexpr int BATCH = 4;
constexpr int CIN   = 128;
constexpr int COUT  = 64;
constexpr int HH    = 128;
constexpr int WW    = 128;
constexpr int HWSZ  = HH * WW;
constexpr int DG    = 16;
constexpr int KK    = 9;
constexpr int OC4   = 27 * DG;   // 432
constexpr int OCP4  = 448;       // padded oc for conv4 MMA (28 x 16)

// Scratch (static device buffers; allocation APIs are forbidden)
__device__ float g_o4[(size_t)BATCH * OC4 * HWSZ];
__device__ __align__(16) float g_wt[(size_t)CIN * KK * COUT];        // deform weight [cin][k][o]
// activations as split bf16 pairs, layout [b][y][px][cin]
__device__ __align__(16) __nv_bfloat16 g_axh[(size_t)BATCH * HWSZ * 192];
__device__ __align__(16) __nv_bfloat16 g_axl[(size_t)BATCH * HWSZ * 192];
__device__ __align__(16) __nv_bfloat16 g_uh[(size_t)BATCH * HWSZ * 64];
__device__ __align__(16) __nv_bfloat16 g_ul[(size_t)BATCH * HWSZ * 64];
__device__ __align__(16) __nv_bfloat16 g_vh[(size_t)BATCH * HWSZ * 64];
__device__ __align__(16) __nv_bfloat16 g_vl[(size_t)BATCH * HWSZ * 64];
// conv weights [k][ocp][cin] split bf16
__device__ __align__(16) __nv_bfloat16 g_w1h[(size_t)9 * 64 * 192];
__device__ __align__(16) __nv_bfloat16 g_w1l[(size_t)9 * 64 * 192];
__device__ __align__(16) __nv_bfloat16 g_w2h[(size_t)9 * 64 * 64];
__device__ __align__(16) __nv_bfloat16 g_w2l[(size_t)9 * 64 * 64];
__device__ __align__(16) __nv_bfloat16 g_w3h[(size_t)9 * 64 * 64];
__device__ __align__(16) __nv_bfloat16 g_w3l[(size_t)9 * 64 * 64];
__device__ __align__(16) __nv_bfloat16 g_w4h[(size_t)9 * OCP4 * 64];
__device__ __align__(16) __nv_bfloat16 g_w4l[(size_t)9 * OCP4 * 64];

// ---------------------------------------------------------------------------
// Helpers
// ---------------------------------------------------------------------------
typedef unsigned long long u64;

__device__ __forceinline__ u64 ffma2(u64 a, u64 b, u64 c) {
    u64 d;
    asm("fma.rn.f32x2 %0, %1, %2, %3;" : "=l"(d) : "l"(a), "l"(b), "l"(c));
    return d;
}
__device__ __forceinline__ u64 pk2(float lo, float hi) {
    u64 r;
    asm("mov.b64 %0, {%1, %2};" : "=l"(r) : "f"(lo), "f"(hi));
    return r;
}
__device__ __forceinline__ float2 upk(u64 v) {
    float2 r;
    asm("mov.b64 {%0, %1}, %2;" : "=f"(r.x), "=f"(r.y) : "l"(v));
    return r;
}
__device__ __forceinline__ float fast_tanh(float x) {
    return 1.f - 2.f / (__expf(2.f * x) + 1.f);
}
__device__ __forceinline__ float fast_sigmoid(float x) {
    return 1.f / (1.f + __expf(-x));
}
__device__ __forceinline__ uint32_t smem_u32(const void* p) {
    uint32_t a;
    asm("{ .reg .u64 t; cvta.to.shared.u64 t, %1; cvt.u32.u64 %0, t; }" : "=r"(a) : "l"(p));
    return a;
}
__device__ __forceinline__ void ldsm_x4(uint32_t& r0, uint32_t& r1,
                                        uint32_t& r2, uint32_t& r3, uint32_t addr) {
    asm volatile("ldmatrix.sync.aligned.m8n8.x4.shared.b16 {%0,%1,%2,%3}, [%4];"
                 : "=r"(r0), "=r"(r1), "=r"(r2), "=r"(r3) : "r"(addr));
}
__device__ __forceinline__ void mma16816(float* d, const uint32_t* a,
                                         uint32_t b0, uint32_t b1) {
    asm volatile(
        "mma.sync.aligned.m16n8k16.row.col.f32.bf16.bf16.f32 "
        "{%0,%1,%2,%3}, {%4,%5,%6,%7}, {%8,%9}, {%0,%1,%2,%3};"
        : "+f"(d[0]), "+f"(d[1]), "+f"(d[2]), "+f"(d[3])
        : "r"(a[0]), "r"(a[1]), "r"(a[2]), "r"(a[3]), "r"(b0), "r"(b1));
}

// ---------------------------------------------------------------------------
// Prep kernels
// ---------------------------------------------------------------------------
__global__ void transpose_weight_k(const float* __restrict__ w, float* __restrict__ wt) {
    int idx = blockIdx.x * blockDim.x + threadIdx.x;
    int n = CIN * KK * COUT;
    if (idx >= n) return;
    int o   = idx % COUT;
    int k   = (idx / COUT) % KK;
    int cin = idx / (COUT * KK);
    wt[idx] = w[((size_t)o * CIN + cin) * KK + k];
}

__global__ void split_w_k(const float* __restrict__ w, __nv_bfloat16* __restrict__ h,
                          __nv_bfloat16* __restrict__ l, int Cout_real, int ocp, int Cin) {
    int idx = blockIdx.x * blockDim.x + threadIdx.x;
    int n = 9 * ocp * Cin;
    if (idx >= n) return;
    int c  = idx % Cin;
    int oc = (idx / Cin) % ocp;
    int k  = idx / (Cin * ocp);
    float v = (oc < Cout_real) ? w[((size_t)oc * Cin + c) * 9 + k] : 0.f;
    __nv_bfloat16 hi = __float2bfloat16(v);
    float hf = __bfloat162float(hi);
    h[idx] = hi;
    l[idx] = __float2bfloat16(v - hf);
}

// Convert extra_feat float [b][192][H][W] -> [b][y][px][192] bf16 hi/lo.
// grid (HH, BATCH), 256 threads, smem tile transpose (32 c x 128 px).
__global__ void __launch_bounds__(256)
convert_x_k(const float* __restrict__ in, __nv_bfloat16* __restrict__ oh,
            __nv_bfloat16* __restrict__ ol) {
    __shared__ __nv_bfloat16 sh[128][40];
    __shared__ __nv_bfloat16 sl[128][40];
    const int tid  = threadIdx.x;
    const int wid  = tid >> 5;
    const int lane = tid & 31;
    const int y = blockIdx.x;
    const int b = blockIdx.y;

    for (int ct = 0; ct < 6; ct++) {
        __syncthreads();
        // read 32 c rows x 128 px (float4 coalesced), split, scatter to smem
        for (int r = 0; r < 4; r++) {
            int c = ct * 32 + r * 8 + wid;
            const float4* src = (const float4*)(in + ((size_t)b * 192 + c) * HWSZ + (size_t)y * WW);
            float4 v = src[lane];
            int px = lane * 4;
            float vv[4] = {v.x, v.y, v.z, v.w};
#pragma unroll
            for (int j = 0; j < 4; j++) {
                __nv_bfloat16 h = __float2bfloat16(vv[j]);
                float hf = __bfloat162float(h);
                sh[px + j][r * 8 + wid] = h;
                sl[px + j][r * 8 + wid] = __float2bfloat16(vv[j] - hf);
            }
        }
        __syncthreads();
        // write out coalesced uint4: 128 px x 32 c = 512 chunks
        for (int i = tid; i < 512; i += 256) {
            int px = i >> 2, cc = (i & 3) * 8;
            size_t dst = ((size_t)(b * HWSZ + y * WW + px)) * 192 + ct * 32 + cc;
            *(uint4*)(oh + dst) = *(uint4*)&sh[px][cc];
            *(uint4*)(ol + dst) = *(uint4*)&sl[px][cc];
        }
    }
}

// ---------------------------------------------------------------------------
// Generic 3x3 conv via mma.sync, pre-split bf16 I/O (copy-only staging).
// CTA: one image row y, 64-oc tile. 256 threads / 8 warps.
// Input: xh/xl [b][y][px][Cin]; weights [k][ocp][cin] hi/lo.
// Output: either float (outf, conv4) or split bf16 pair [b][y][px][64].
// grid = (HH, ocp/64, BATCH).
// ---------------------------------------------------------------------------
constexpr int LDX = 72;
constexpr int LDW = 72;
constexpr uint32_t SX_H = 0;
constexpr uint32_t SX_L = SX_H + 130 * LDX * 2;        // 18720
constexpr uint32_t SW_H = SX_L + 130 * LDX * 2;        // 37440
constexpr uint32_t SW_L = SW_H + 3 * 64 * LDW * 2;     // 65088
constexpr uint32_t SMEMC = SW_L + 3 * 64 * LDW * 2 + 64; // 92800

__global__ void __launch_bounds__(256, 2)
conv_mma_k(const __nv_bfloat16* __restrict__ xh, const __nv_bfloat16* __restrict__ xl,
           const __nv_bfloat16* __restrict__ wh, const __nv_bfloat16* __restrict__ wl,
           const float* __restrict__ bias,
           float* __restrict__ outf,
           __nv_bfloat16* __restrict__ outh, __nv_bfloat16* __restrict__ outl,
           int Cin, int ocp, int Cout_real, int lrelu) {
    extern __shared__ char sm[];
    const uint32_t sbase = smem_u32(sm);

    const int tid  = threadIdx.x;
    const int w    = tid >> 5;
    const int lane = tid & 31;
    const int y = blockIdx.x;
    const int m = blockIdx.y;
    const int b = blockIdx.z;
    const int oc0  = m * 64;
    const int w_oc = w & 3;
    const int w_px = w >> 2;

    __nv_bfloat16* sxh = (__nv_bfloat16*)(sm + SX_H);
    __nv_bfloat16* sxl = (__nv_bfloat16*)(sm + SX_L);
    __nv_bfloat16* swh = (__nv_bfloat16*)(sm + SW_H);
    __nv_bfloat16* swl = (__nv_bfloat16*)(sm + SW_L);

    // zero border px rows (0 and 129) once
    for (int i = tid; i < LDX; i += 256) {
        sxh[i] = __float2bfloat16(0.f);
        sxl[i] = __float2bfloat16(0.f);
        sxh[129 * LDX + i] = __float2bfloat16(0.f);
        sxl[129 * LDX + i] = __float2bfloat16(0.f);
    }

    float d[8][4];
#pragma unroll
    for (int nt = 0; nt < 8; nt++)
#pragma unroll
        for (int j = 0; j < 4; j++) d[nt][j] = 0.f;

    const int a_rl = w_oc * 16 + (lane & 15);
    const int a_ko = (lane >> 4) * 8;
    const int b_r  = lane & 7;
    const int b_ko = ((lane >> 3) & 1) * 8;
    const int b_seg = lane >> 4;

    const int nslab = Cin >> 6;
    for (int sl = 0; sl < nslab; sl++) {
        for (int di = -1; di <= 1; di++) {
            __syncthreads();
            // --- stage x row (y+di), slab sl: pure uint4 copies ---
            {
                const int yy = y + di;
                const bool valid = (yy >= 0) && (yy < HH);
                const size_t rowbase = ((size_t)(b * HH + (valid ? yy : 0)) * WW) * Cin + sl * 64;
                const uint4 z = make_uint4(0, 0, 0, 0);
                for (int i = tid; i < 1024; i += 256) {
                    int px = i >> 3, cc = (i & 7) * 8;
                    size_t src = rowbase + (size_t)px * Cin + cc;
                    uint32_t off = (uint32_t)((1 + px) * LDX + cc);
                    *(uint4*)&sxh[off] = valid ? *(const uint4*)(xh + src) : z;
                    *(uint4*)&sxl[off] = valid ? *(const uint4*)(xl + src) : z;
                }
            }
            // --- stage weights for the 3 taps of this di, slab sl ---
            for (int i = tid; i < 3 * 512; i += 256) {
                int t = i >> 9, r = i & 511;
                int ocl = r >> 3, cc = (r & 7) * 8;
                size_t gidx = ((size_t)((di + 1) * 3 + t) * ocp + oc0 + ocl) * Cin
                            + (size_t)sl * 64 + cc;
                *(uint4*)&swh[(t * 64 + ocl) * LDW + cc] = *(const uint4*)(wh + gidx);
                *(uint4*)&swl[(t * 64 + ocl) * LDW + cc] = *(const uint4*)(wl + gidx);
            }
            __syncthreads();

#pragma unroll
            for (int djs = 0; djs < 3; djs++) {
#pragma unroll
                for (int kc = 0; kc < 4; kc++) {
                    uint32_t aH[4], aL[4];
                    {
                        uint32_t off = (uint32_t)((djs * 64 + a_rl) * LDW + kc * 16 + a_ko) * 2;
                        ldsm_x4(aH[0], aH[1], aH[2], aH[3], sbase + SW_H + off);
                        ldsm_x4(aL[0], aL[1], aL[2], aL[3], sbase + SW_L + off);
                    }
#pragma unroll
                    for (int nt2 = 0; nt2 < 4; nt2++) {
                        const int row = djs + w_px * 64 + nt2 * 16 + b_seg * 8 + b_r;
                        uint32_t off = (uint32_t)(row * LDX + kc * 16 + b_ko) * 2;
                        uint32_t bh0, bh1, bh2, bh3, bl0, bl1, bl2, bl3;
                        ldsm_x4(bh0, bh1, bh2, bh3, sbase + SX_H + off);
                        ldsm_x4(bl0, bl1, bl2, bl3, sbase + SX_L + off);
                        float* d0 = d[nt2 * 2];
                        float* d1 = d[nt2 * 2 + 1];
                        mma16816(d0, aH, bh0, bh1);
                        mma16816(d0, aH, bl0, bl1);
                        mma16816(d0, aL, bh0, bh1);
                        mma16816(d1, aH, bh2, bh3);
                        mma16816(d1, aH, bl2, bl3);
                        mma16816(d1, aL, bh2, bh3);
                    }
                }
            }
        }
    }

    const int g   = lane >> 2;
    const int tig = lane & 3;

    if (outf != nullptr) {
        // float epilogue (conv4): direct global stores
#pragma unroll
        for (int nt = 0; nt < 8; nt++) {
            int px  = w_px * 64 + nt * 8 + tig * 2;
            int o0  = oc0 + w_oc * 16 + g;
            int o1  = o0 + 8;
            size_t rowoff = (size_t)y * WW + px;
            if (o0 < Cout_real) {
                float bv = bias[o0];
                *(float2*)(outf + ((size_t)b * Cout_real + o0) * HWSZ + rowoff)
                    = make_float2(d[nt][0] + bv, d[nt][1] + bv);
            }
            if (o1 < Cout_real) {
                float bv = bias[o1];
                *(float2*)(outf + ((size_t)b * Cout_real + o1) * HWSZ + rowoff)
                    = make_float2(d[nt][2] + bv, d[nt][3] + bv);
            }
        }
    } else {
        // bf16-pair epilogue: bias+lrelu, split, smem transpose, coalesced store
        __syncthreads();   // all MMA reads of sx done; reuse sx region
#pragma unroll
        for (int nt = 0; nt < 8; nt++) {
            int px = w_px * 64 + nt * 8 + tig * 2;
            int ol0 = w_oc * 16 + g;
            int ol1 = ol0 + 8;
            float bv0 = bias[ol0], bv1 = bias[ol1];
#pragma unroll
            for (int j = 0; j < 4; j++) {
                int ocl = (j < 2) ? ol0 : ol1;
                float v = d[nt][j] + ((j < 2) ? bv0 : bv1);
                if (lrelu) v = (v >= 0.f) ? v : 0.1f * v;
                __nv_bfloat16 h = __float2bfloat16(v);
                float hf = __bfloat162float(h);
                int pxe = px + (j & 1);
                sxh[pxe * LDX + ocl] = h;
                sxl[pxe * LDX + ocl] = __float2bfloat16(v - hf);
            }
        }
        __syncthreads();
        for (int i = tid; i < 1024; i += 256) {
            int px = i >> 3, cc = (i & 7) * 8;
            size_t dst = ((size_t)(b * HH + y) * WW + px) * 64 + cc;
            *(uint4*)(outh + dst) = *(uint4*)&sxh[px * LDX + cc];
            *(uint4*)(outl + dst) = *(uint4*)&sxl[px * LDX + cc];
        }
    }
}

// ---------------------------------------------------------------------------
// Deformable conv — R4 best version (+ fast activations, verified neutral).
// ---------------------------------------------------------------------------
__global__ void __launch_bounds__(128, 4)
deform_k(const float* __restrict__ x, const float* __restrict__ o4,
         const float* __restrict__ wt, const float* __restrict__ bias,
         float* __restrict__ out) {
    const int tx = threadIdx.x, ty = threadIdx.y;
    const int tid = ty * 32 + tx;
    const int b   = blockIdx.z;
    const int px  = blockIdx.x * 32 + tx;
    const int py  = blockIdx.y * 4 + ty;
    const int p   = py * WW + px;

    __shared__ __align__(16) u64 s_w[8 * 9 * 32];

    u64 acc[32];
#pragma unroll
    for (int q = 0; q < 32; q++) acc[q] = 0ull;

    const float* xb = x + (size_t)b * CIN * HWSZ;
    const float* ob = o4 + (size_t)b * OC4 * HWSZ;

    for (int g = 0; g < DG; g++) {
        __syncthreads();
        const u64* wg = (const u64*)(wt + (size_t)g * 8 * 9 * 64);
        for (int i = tid; i < 8 * 9 * 32; i += 128) s_w[i] = wg[i];
        __syncthreads();

        const float* xg = xb + (size_t)g * 8 * HWSZ;

        for (int k = 0; k < KK; k++) {
            float dy = 10.f * fast_tanh(ob[(size_t)(g * 18 + 2 * k) * HWSZ + p]);
            float dx = 10.f * fast_tanh(ob[(size_t)(g * 18 + 2 * k + 1) * HWSZ + p]);
            float m  = fast_sigmoid(ob[(size_t)(288 + g * 9 + k) * HWSZ + p]);

            float fy = (float)py - 1.f + (float)(k / 3) + dy;
            float fx = (float)px - 1.f + (float)(k % 3) + dx;
            float y0f = floorf(fy), x0f = floorf(fx);
            float ly = fy - y0f, lx = fx - x0f;
            int y0 = (int)y0f, x0 = (int)x0f;
            int y1 = y0 + 1, x1 = x0 + 1;

            bool vy0 = (y0 >= 0) && (y0 < HH);
            bool vy1 = (y1 >= 0) && (y1 < HH);
            bool vx0 = (x0 >= 0) && (x0 < WW);
            bool vx1 = (x1 >= 0) && (x1 < WW);

            float w00 = (1.f - ly) * (1.f - lx) * ((vy0 && vx0) ? m : 0.f);
            float w01 = (1.f - ly) * lx         * ((vy0 && vx1) ? m : 0.f);
            float w10 = ly * (1.f - lx)         * ((vy1 && vx0) ? m : 0.f);
            float w11 = ly * lx                 * ((vy1 && vx1) ? m : 0.f);

            int yc0 = min(max(y0, 0), HH - 1);
            int yc1 = min(max(y1, 0), HH - 1);
            int xc0 = min(max(x0, 0), WW - 1);
            int xc1 = min(max(x1, 0), WW - 1);
            int i00 = yc0 * WW + xc0, i01 = yc0 * WW + xc1;
            int i10 = yc1 * WW + xc0, i11 = yc1 * WW + xc1;

#pragma unroll
            for (int c = 0; c < 8; c++) {
                const float* xc = xg + (size_t)c * HWSZ;
                float v = w00 * xc[i00] + w01 * xc[i01] + w10 * xc[i10] + w11 * xc[i11];
                u64 v2 = pk2(v, v);
                const ulonglong2* wp = (const ulonglong2*)&s_w[(c * 9 + k) * 32];
#pragma unroll
                for (int q = 0; q < 16; q++) {
                    ulonglong2 wq = wp[q];
                    acc[q * 2 + 0] = ffma2(v2, wq.x, acc[q * 2 + 0]);
                    acc[q * 2 + 1] = ffma2(v2, wq.y, acc[q * 2 + 1]);
                }
            }
        }
    }

    float* outb = out + (size_t)b * COUT * HWSZ + p;
#pragma unroll
    for (int q = 0; q < 32; q++) {
        float2 v = upk(acc[q]);
        outb[(size_t)(2 * q + 0) * HWSZ] = v.x + bias[2 * q + 0];
        outb[(size_t)(2 * q + 1) * HWSZ] = v.y + bias[2 * q + 1];
    }
}

// ---------------------------------------------------------------------------
// Launcher
// ---------------------------------------------------------------------------
extern "C" void kernel_launch(void* const* d_in, const int* in_sizes, int n_in,
                              void* d_out, int out_size) {
    const float* x          = (const float*)d_in[0];
    const float* extra_feat = (const float*)d_in[1];
    const float* w1 = (const float*)d_in[2];
    const float* b1 = (const float*)d_in[3];
    const float* w2 = (const float*)d_in[4];
    const float* b2 = (const float*)d_in[5];
    const float* w3 = (const float*)d_in[6];
    const float* b3 = (const float*)d_in[7];
    const float* w4 = (const float*)d_in[8];
    const float* b4 = (const float*)d_in[9];
    const float* weight = (const float*)d_in[10];
    const float* bias   = (const float*)d_in[11];
    float* out = (float*)d_out;

    float *o4, *wt;
    __nv_bfloat16 *axh, *axl, *uh, *ul, *vh, *vl;
    __nv_bfloat16 *w1h, *w1l, *w2h, *w2l, *w3h, *w3l, *w4h, *w4l;
    cudaGetSymbolAddress((void**)&o4, g_o4);
    cudaGetSymbolAddress((void**)&wt, g_wt);
    cudaGetSymbolAddress((void**)&axh, g_axh);
    cudaGetSymbolAddress((void**)&axl, g_axl);
    cudaGetSymbolAddress((void**)&uh, g_uh);
    cudaGetSymbolAddress((void**)&ul, g_ul);
    cudaGetSymbolAddress((void**)&vh, g_vh);
    cudaGetSymbolAddress((void**)&vl, g_vl);
    cudaGetSymbolAddress((void**)&w1h, g_w1h);
    cudaGetSymbolAddress((void**)&w1l, g_w1l);
    cudaGetSymbolAddress((void**)&w2h, g_w2h);
    cudaGetSymbolAddress((void**)&w2l, g_w2l);
    cudaGetSymbolAddress((void**)&w3h, g_w3h);
    cudaGetSymbolAddress((void**)&w3l, g_w3l);
    cudaGetSymbolAddress((void**)&w4h, g_w4h);
    cudaGetSymbolAddress((void**)&w4l, g_w4l);

    cudaFuncSetAttribute(conv_mma_k, cudaFuncAttributeMaxDynamicSharedMemorySize, SMEMC);

    // prep: deform weight transpose, conv weight splits, extra_feat convert
    {
        int n = CIN * KK * COUT;
        transpose_weight_k<<<(n + 255) / 256, 256>>>(weight, wt);
        int n1 = 9 * 64 * 192;
        split_w_k<<<(n1 + 255) / 256, 256>>>(w1, w1h, w1l, 64, 64, 192);
        int n2 = 9 * 64 * 64;
        split_w_k<<<(n2 + 255) / 256, 256>>>(w2, w2h, w2l, 64, 64, 64);
        split_w_k<<<(n2 + 255) / 256, 256>>>(w3, w3h, w3l, 64, 64, 64);
        int n4 = 9 * OCP4 * 64;
        split_w_k<<<(n4 + 255) / 256, 256>>>(w4, w4h, w4l, OC4, OCP4, 64);
        convert_x_k<<<dim3(HH, BATCH), 256>>>(extra_feat, axh, axl);
    }

    // conv1: ax (192ch) -> u (64ch bf16 pair), lrelu
    conv_mma_k<<<dim3(HH, 1, BATCH), 256, SMEMC>>>(axh, axl, w1h, w1l, b1,
                                                   nullptr, uh, ul, 192, 64, 64, 1);
    // conv2: u -> v, lrelu
    conv_mma_k<<<dim3(HH, 1, BATCH), 256, SMEMC>>>(uh, ul, w2h, w2l, b2,
                                                   nullptr, vh, vl, 64, 64, 64, 1);
    // conv3: v -> u, lrelu
    conv_mma_k<<<dim3(HH, 1, BATCH), 256, SMEMC>>>(vh, vl, w3h, w3l, b3,
                                                   nullptr, uh, ul, 64, 64, 64, 1);
    // conv4: u -> o4 (432ch float, +bias, no activation)
    conv_mma_k<<<dim3(HH, OCP4 / 64, BATCH), 256, SMEMC>>>(uh, ul, w4h, w4l, b4,
                                                           o4, nullptr, nullptr, 64, OCP4, OC4, 0);
    // deformable conv: x + o4 -> out
    deform_k<<<dim3(WW / 32, HH / 4, BATCH), dim3(32, 4)>>>(x, o4, wt, bias, out);
}

// round 15
// speedup vs baseline: 1.4775x; 1.4775x over previous
#include <cuda_runtime.h>
#include <cuda_bf16.h>
#include <math.h>
#include <stdint.h>

// Problem constants
constexpr int BATCH = 4;
constexpr int CIN   = 128;
constexpr int COUT  = 64;
constexpr int HH    = 128;
constexpr int WW    = 128;
constexpr int HWSZ  = HH * WW;
constexpr int DG    = 16;
constexpr int KK    = 9;
constexpr int OC4   = 27 * DG;   // 432
constexpr int OCP4  = 448;       // padded oc for conv4 MMA (28 x 16)

// Scratch (static device buffers; allocation APIs are forbidden)
__device__ float g_t1[(size_t)BATCH * COUT * HWSZ];
__device__ float g_t2[(size_t)BATCH * COUT * HWSZ];
__device__ float g_o4[(size_t)BATCH * OC4 * HWSZ];
__device__ __align__(16) float g_wt[(size_t)CIN * KK * COUT];        // deform weight [cin][k][o]
// pre-split activations [b][y][px][cin] bf16 hi/lo
__device__ __align__(16) __nv_bfloat16 g_axh[(size_t)BATCH * HWSZ * 192];
__device__ __align__(16) __nv_bfloat16 g_axl[(size_t)BATCH * HWSZ * 192];
__device__ __align__(16) __nv_bfloat16 g_uh[(size_t)BATCH * HWSZ * 64];
__device__ __align__(16) __nv_bfloat16 g_ul[(size_t)BATCH * HWSZ * 64];
// conv weights [k][ocp][cin] split bf16
__device__ __align__(16) __nv_bfloat16 g_w1h[(size_t)9 * 64 * 192];
__device__ __align__(16) __nv_bfloat16 g_w1l[(size_t)9 * 64 * 192];
__device__ __align__(16) __nv_bfloat16 g_w2h[(size_t)9 * 64 * 64];
__device__ __align__(16) __nv_bfloat16 g_w2l[(size_t)9 * 64 * 64];
__device__ __align__(16) __nv_bfloat16 g_w3h[(size_t)9 * 64 * 64];
__device__ __align__(16) __nv_bfloat16 g_w3l[(size_t)9 * 64 * 64];
__device__ __align__(16) __nv_bfloat16 g_w4h[(size_t)9 * OCP4 * 64];
__device__ __align__(16) __nv_bfloat16 g_w4l[(size_t)9 * OCP4 * 64];

// ---------------------------------------------------------------------------
// Helpers
// ---------------------------------------------------------------------------
typedef unsigned long long u64;

__device__ __forceinline__ u64 ffma2(u64 a, u64 b, u64 c) {
    u64 d;
    asm("fma.rn.f32x2 %0, %1, %2, %3;" : "=l"(d) : "l"(a), "l"(b), "l"(c));
    return d;
}
__device__ __forceinline__ u64 pk2(float lo, float hi) {
    u64 r;
    asm("mov.b64 %0, {%1, %2};" : "=l"(r) : "f"(lo), "f"(hi));
    return r;
}
__device__ __forceinline__ float2 upk(u64 v) {
    float2 r;
    asm("mov.b64 {%0, %1}, %2;" : "=f"(r.x), "=f"(r.y) : "l"(v));
    return r;
}
__device__ __forceinline__ float fast_tanh(float x) {
    return 1.f - 2.f / (__expf(2.f * x) + 1.f);
}
__device__ __forceinline__ float fast_sigmoid(float x) {
    return 1.f / (1.f + __expf(-x));
}
__device__ __forceinline__ uint32_t smem_u32(const void* p) {
    uint32_t a;
    asm("{ .reg .u64 t; cvta.to.shared.u64 t, %1; cvt.u32.u64 %0, t; }" : "=r"(a) : "l"(p));
    return a;
}
__device__ __forceinline__ void ldsm_x4(uint32_t& r0, uint32_t& r1,
                                        uint32_t& r2, uint32_t& r3, uint32_t addr) {
    asm volatile("ldmatrix.sync.aligned.m8n8.x4.shared.b16 {%0,%1,%2,%3}, [%4];"
                 : "=r"(r0), "=r"(r1), "=r"(r2), "=r"(r3) : "r"(addr));
}
__device__ __forceinline__ void mma16816(float* d, const uint32_t* a,
                                         uint32_t b0, uint32_t b1) {
    asm volatile(
        "mma.sync.aligned.m16n8k16.row.col.f32.bf16.bf16.f32 "
        "{%0,%1,%2,%3}, {%4,%5,%6,%7}, {%8,%9}, {%0,%1,%2,%3};"
        : "+f"(d[0]), "+f"(d[1]), "+f"(d[2]), "+f"(d[3])
        : "r"(a[0]), "r"(a[1]), "r"(a[2]), "r"(a[3]), "r"(b0), "r"(b1));
}

// ---------------------------------------------------------------------------
// Prep kernels
// ---------------------------------------------------------------------------
__global__ void transpose_weight_k(const float* __restrict__ w, float* __restrict__ wt) {
    int idx = blockIdx.x * blockDim.x + threadIdx.x;
    int n = CIN * KK * COUT;
    if (idx >= n) return;
    int o   = idx % COUT;
    int k   = (idx / COUT) % KK;
    int cin = idx / (COUT * KK);
    wt[idx] = w[((size_t)o * CIN + cin) * KK + k];
}

__global__ void split_w_k(const float* __restrict__ w, __nv_bfloat16* __restrict__ h,
                          __nv_bfloat16* __restrict__ l, int Cout_real, int ocp, int Cin) {
    int idx = blockIdx.x * blockDim.x + threadIdx.x;
    int n = 9 * ocp * Cin;
    if (idx >= n) return;
    int c  = idx % Cin;
    int oc = (idx / Cin) % ocp;
    int k  = idx / (Cin * ocp);
    float v = (oc < Cout_real) ? w[((size_t)oc * Cin + c) * 9 + k] : 0.f;
    __nv_bfloat16 hi = __float2bfloat16(v);
    float hf = __bfloat162float(hi);
    h[idx] = hi;
    l[idx] = __float2bfloat16(v - hf);
}

// Convert float NCHW -> [b][y][px][Cin] bf16 hi/lo. grid (HH, BATCH), 256 thr.
__global__ void __launch_bounds__(256)
convert_k(const float* __restrict__ in, __nv_bfloat16* __restrict__ oh,
          __nv_bfloat16* __restrict__ ol, int Cin) {
    __shared__ __nv_bfloat16 sh[128][40];
    __shared__ __nv_bfloat16 sl[128][40];
    const int tid  = threadIdx.x;
    const int wid  = tid >> 5;
    const int lane = tid & 31;
    const int y = blockIdx.x;
    const int b = blockIdx.y;
    const int nct = Cin >> 5;

    for (int ct = 0; ct < nct; ct++) {
        __syncthreads();
        for (int r = 0; r < 4; r++) {
            int c = ct * 32 + r * 8 + wid;
            const float4* src = (const float4*)(in + ((size_t)b * Cin + c) * HWSZ + (size_t)y * WW);
            float4 v = src[lane];
            int px = lane * 4;
            float vv[4] = {v.x, v.y, v.z, v.w};
#pragma unroll
            for (int j = 0; j < 4; j++) {
                __nv_bfloat16 h = __float2bfloat16(vv[j]);
                float hf = __bfloat162float(h);
                sh[px + j][r * 8 + wid] = h;
                sl[px + j][r * 8 + wid] = __float2bfloat16(vv[j] - hf);
            }
        }
        __syncthreads();
        for (int i = tid; i < 512; i += 256) {
            int px = i >> 2, cc = (i & 3) * 8;
            size_t dst = ((size_t)(b * HWSZ + y * WW + px)) * Cin + ct * 32 + cc;
            *(uint4*)(oh + dst) = *(uint4*)&sh[px][cc];
            *(uint4*)(ol + dst) = *(uint4*)&sl[px][cc];
        }
    }
}

// ---------------------------------------------------------------------------
// Shared smem layout for conv kernels
// ---------------------------------------------------------------------------
constexpr int LDX = 72;
constexpr int LDW = 72;
constexpr uint32_t SX_H = 0;
constexpr uint32_t SX_L = SX_H + 130 * LDX * 2;        // 18720
constexpr uint32_t SW_H = SX_L + 130 * LDX * 2;        // 37440
constexpr uint32_t SW_L = SW_H + 3 * 64 * LDW * 2;     // 65088
constexpr uint32_t SMEMC = SW_L + 3 * 64 * LDW * 2 + 64; // 92800

// ---------------------------------------------------------------------------
// conv_mma_k — EXACT R13 version (float input, in-kernel split staging,
// float/lrelu epilogue). Used for conv2 and conv3.
// ---------------------------------------------------------------------------
__global__ void __launch_bounds__(256, 2)
conv_mma_k(const float* __restrict__ in,
           const __nv_bfloat16* __restrict__ wh, const __nv_bfloat16* __restrict__ wl,
           const float* __restrict__ bias, float* __restrict__ out,
           int Cin, int ocp, int Cout_real, int lrelu) {
    extern __shared__ char sm[];
    const uint32_t sbase = smem_u32(sm);

    const int tid  = threadIdx.x;
    const int w    = tid >> 5;
    const int lane = tid & 31;
    const int y = blockIdx.x;
    const int m = blockIdx.y;
    const int b = blockIdx.z;
    const int oc0  = m * 64;
    const int w_oc = w & 3;
    const int w_px = w >> 2;

    __nv_bfloat16* sxh = (__nv_bfloat16*)(sm + SX_H);
    __nv_bfloat16* sxl = (__nv_bfloat16*)(sm + SX_L);
    __nv_bfloat16* swh = (__nv_bfloat16*)(sm + SW_H);
    __nv_bfloat16* swl = (__nv_bfloat16*)(sm + SW_L);

    for (int i = tid; i < LDX; i += 256) {
        sxh[i] = __float2bfloat16(0.f);
        sxl[i] = __float2bfloat16(0.f);
        sxh[129 * LDX + i] = __float2bfloat16(0.f);
        sxl[129 * LDX + i] = __float2bfloat16(0.f);
    }

    float d[8][4];
#pragma unroll
    for (int nt = 0; nt < 8; nt++)
#pragma unroll
        for (int j = 0; j < 4; j++) d[nt][j] = 0.f;

    const float* inb = in + (size_t)b * Cin * HWSZ;

    const int a_rl = w_oc * 16 + (lane & 15);
    const int a_ko = (lane >> 4) * 8;
    const int b_r  = lane & 7;
    const int b_ko = ((lane >> 3) & 1) * 8;
    const int b_seg = lane >> 4;

    const int nslab = Cin >> 6;
    for (int sl = 0; sl < nslab; sl++) {
        for (int di = -1; di <= 1; di++) {
            __syncthreads();
            {
                const int yy = y + di;
                const bool valid = (yy >= 0) && (yy < HH);
                const float* trow = inb + ((size_t)sl * 64) * HWSZ + (size_t)(valid ? yy : 0) * WW;
                for (int i = tid; i < 64 * 128; i += 256) {
                    int c = i >> 7, px = i & 127;
                    float v = valid ? trow[(size_t)c * HWSZ + px] : 0.f;
                    __nv_bfloat16 h = __float2bfloat16(v);
                    float hf = __bfloat162float(h);
                    sxh[(1 + px) * LDX + c] = h;
                    sxl[(1 + px) * LDX + c] = __float2bfloat16(v - hf);
                }
            }
            for (int i = tid; i < 3 * 512; i += 256) {
                int t = i >> 9, r = i & 511;
                int ocl = r >> 3, cc = (r & 7) * 8;
                size_t gidx = ((size_t)((di + 1) * 3 + t) * ocp + oc0 + ocl) * Cin
                            + (size_t)sl * 64 + cc;
                *(uint4*)&swh[(t * 64 + ocl) * LDW + cc] = *(const uint4*)(wh + gidx);
                *(uint4*)&swl[(t * 64 + ocl) * LDW + cc] = *(const uint4*)(wl + gidx);
            }
            __syncthreads();

#pragma unroll
            for (int djs = 0; djs < 3; djs++) {
#pragma unroll
                for (int kc = 0; kc < 4; kc++) {
                    uint32_t aH[4], aL[4];
                    {
                        uint32_t off = (uint32_t)((djs * 64 + a_rl) * LDW + kc * 16 + a_ko) * 2;
                        ldsm_x4(aH[0], aH[1], aH[2], aH[3], sbase + SW_H + off);
                        ldsm_x4(aL[0], aL[1], aL[2], aL[3], sbase + SW_L + off);
                    }
#pragma unroll
                    for (int nt2 = 0; nt2 < 4; nt2++) {
                        const int row = djs + w_px * 64 + nt2 * 16 + b_seg * 8 + b_r;
                        uint32_t off = (uint32_t)(row * LDX + kc * 16 + b_ko) * 2;
                        uint32_t bh0, bh1, bh2, bh3, bl0, bl1, bl2, bl3;
                        ldsm_x4(bh0, bh1, bh2, bh3, sbase + SX_H + off);
                        ldsm_x4(bl0, bl1, bl2, bl3, sbase + SX_L + off);
                        float* d0 = d[nt2 * 2];
                        float* d1 = d[nt2 * 2 + 1];
                        mma16816(d0, aH, bh0, bh1);
                        mma16816(d0, aH, bl0, bl1);
                        mma16816(d0, aL, bh0, bh1);
                        mma16816(d1, aH, bh2, bh3);
                        mma16816(d1, aH, bl2, bl3);
                        mma16816(d1, aL, bh2, bh3);
                    }
                }
            }
        }
    }

    const int g   = lane >> 2;
    const int tig = lane & 3;
#pragma unroll
    for (int nt = 0; nt < 8; nt++) {
        int px  = w_px * 64 + nt * 8 + tig * 2;
        int o0  = oc0 + w_oc * 16 + g;
        int o1  = o0 + 8;
        size_t rowoff = (size_t)y * WW + px;
        if (o0 < Cout_real) {
            float bv = bias[o0];
            float vx = d[nt][0] + bv, vy = d[nt][1] + bv;
            if (lrelu) {
                vx = (vx >= 0.f) ? vx : 0.1f * vx;
                vy = (vy >= 0.f) ? vy : 0.1f * vy;
            }
            *(float2*)(out + ((size_t)b * Cout_real + o0) * HWSZ + rowoff) = make_float2(vx, vy);
        }
        if (o1 < Cout_real) {
            float bv = bias[o1];
            float vx = d[nt][2] + bv, vy = d[nt][3] + bv;
            if (lrelu) {
                vx = (vx >= 0.f) ? vx : 0.1f * vx;
                vy = (vy >= 0.f) ? vy : 0.1f * vy;
            }
            *(float2*)(out + ((size_t)b * Cout_real + o1) * HWSZ + rowoff) = make_float2(vx, vy);
        }
    }
}

// ---------------------------------------------------------------------------
// conv_mma_pre_k — pre-split bf16 input (copy-only staging), float epilogue.
// Used for conv1 (Cin=192) and conv4 (Cin=64, 7 oc-tiles).
// ---------------------------------------------------------------------------
__global__ void __launch_bounds__(256, 2)
conv_mma_pre_k(const __nv_bfloat16* __restrict__ xh, const __nv_bfloat16* __restrict__ xl,
               const __nv_bfloat16* __restrict__ wh, const __nv_bfloat16* __restrict__ wl,
               const float* __restrict__ bias, float* __restrict__ out,
               int Cin, int ocp, int Cout_real, int lrelu) {
    extern __shared__ char sm[];
    const uint32_t sbase = smem_u32(sm);

    const int tid  = threadIdx.x;
    const int w    = tid >> 5;
    const int lane = tid & 31;
    const int y = blockIdx.x;
    const int m = blockIdx.y;
    const int b = blockIdx.z;
    const int oc0  = m * 64;
    const int w_oc = w & 3;
    const int w_px = w >> 2;

    __nv_bfloat16* sxh = (__nv_bfloat16*)(sm + SX_H);
    __nv_bfloat16* sxl = (__nv_bfloat16*)(sm + SX_L);
    __nv_bfloat16* swh = (__nv_bfloat16*)(sm + SW_H);
    __nv_bfloat16* swl = (__nv_bfloat16*)(sm + SW_L);

    for (int i = tid; i < LDX; i += 256) {
        sxh[i] = __float2bfloat16(0.f);
        sxl[i] = __float2bfloat16(0.f);
        sxh[129 * LDX + i] = __float2bfloat16(0.f);
        sxl[129 * LDX + i] = __float2bfloat16(0.f);
    }

    float d[8][4];
#pragma unroll
    for (int nt = 0; nt < 8; nt++)
#pragma unroll
        for (int j = 0; j < 4; j++) d[nt][j] = 0.f;

    const int a_rl = w_oc * 16 + (lane & 15);
    const int a_ko = (lane >> 4) * 8;
    const int b_r  = lane & 7;
    const int b_ko = ((lane >> 3) & 1) * 8;
    const int b_seg = lane >> 4;

    const int nslab = Cin >> 6;
    for (int sl = 0; sl < nslab; sl++) {
        for (int di = -1; di <= 1; di++) {
            __syncthreads();
            // copy-only x staging from pre-split [b][y][px][Cin]
            {
                const int yy = y + di;
                const bool valid = (yy >= 0) && (yy < HH);
                const size_t rowbase = ((size_t)(b * HH + (valid ? yy : 0)) * WW) * Cin + sl * 64;
                const uint4 z = make_uint4(0, 0, 0, 0);
                for (int i = tid; i < 1024; i += 256) {
                    int px = i >> 3, cc = (i & 7) * 8;
                    size_t src = rowbase + (size_t)px * Cin + cc;
                    uint32_t off = (uint32_t)((1 + px) * LDX + cc);
                    *(uint4*)&sxh[off] = valid ? *(const uint4*)(xh + src) : z;
                    *(uint4*)&sxl[off] = valid ? *(const uint4*)(xl + src) : z;
                }
            }
            for (int i = tid; i < 3 * 512; i += 256) {
                int t = i >> 9, r = i & 511;
                int ocl = r >> 3, cc = (r & 7) * 8;
                size_t gidx = ((size_t)((di + 1) * 3 + t) * ocp + oc0 + ocl) * Cin
                            + (size_t)sl * 64 + cc;
                *(uint4*)&swh[(t * 64 + ocl) * LDW + cc] = *(const uint4*)(wh + gidx);
                *(uint4*)&swl[(t * 64 + ocl) * LDW + cc] = *(const uint4*)(wl + gidx);
            }
            __syncthreads();

#pragma unroll
            for (int djs = 0; djs < 3; djs++) {
#pragma unroll
                for (int kc = 0; kc < 4; kc++) {
                    uint32_t aH[4], aL[4];
                    {
                        uint32_t off = (uint32_t)((djs * 64 + a_rl) * LDW + kc * 16 + a_ko) * 2;
                        ldsm_x4(aH[0], aH[1], aH[2], aH[3], sbase + SW_H + off);
                        ldsm_x4(aL[0], aL[1], aL[2], aL[3], sbase + SW_L + off);
                    }
#pragma unroll
                    for (int nt2 = 0; nt2 < 4; nt2++) {
                        const int row = djs + w_px * 64 + nt2 * 16 + b_seg * 8 + b_r;
                        uint32_t off = (uint32_t)(row * LDX + kc * 16 + b_ko) * 2;
                        uint32_t bh0, bh1, bh2, bh3, bl0, bl1, bl2, bl3;
                        ldsm_x4(bh0, bh1, bh2, bh3, sbase + SX_H + off);
                        ldsm_x4(bl0, bl1, bl2, bl3, sbase + SX_L + off);
                        float* d0 = d[nt2 * 2];
                        float* d1 = d[nt2 * 2 + 1];
                        mma16816(d0, aH, bh0, bh1);
                        mma16816(d0, aH, bl0, bl1);
                        mma16816(d0, aL, bh0, bh1);
                        mma16816(d1, aH, bh2, bh3);
                        mma16816(d1, aH, bl2, bl3);
                        mma16816(d1, aL, bh2, bh3);
                    }
                }
            }
        }
    }

    const int g   = lane >> 2;
    const int tig = lane & 3;
#pragma unroll
    for (int nt = 0; nt < 8; nt++) {
        int px  = w_px * 64 + nt * 8 + tig * 2;
        int o0  = oc0 + w_oc * 16 + g;
        int o1  = o0 + 8;
        size_t rowoff = (size_t)y * WW + px;
        if (o0 < Cout_real) {
            float bv = bias[o0];
            float vx = d[nt][0] + bv, vy = d[nt][1] + bv;
            if (lrelu) {
                vx = (vx >= 0.f) ? vx : 0.1f * vx;
                vy = (vy >= 0.f) ? vy : 0.1f * vy;
            }
            *(float2*)(out + ((size_t)b * Cout_real + o0) * HWSZ + rowoff) = make_float2(vx, vy);
        }
        if (o1 < Cout_real) {
            float bv = bias[o1];
            float vx = d[nt][2] + bv, vy = d[nt][3] + bv;
            if (lrelu) {
                vx = (vx >= 0.f) ? vx : 0.1f * vx;
                vy = (vy >= 0.f) ? vy : 0.1f * vy;
            }
            *(float2*)(out + ((size_t)b * Cout_real + o1) * HWSZ + rowoff) = make_float2(vx, vy);
        }
    }
}

// ---------------------------------------------------------------------------
// Deformable conv — R4 best version (+ fast activations, verified neutral).
// ---------------------------------------------------------------------------
__global__ void __launch_bounds__(128, 4)
deform_k(const float* __restrict__ x, const float* __restrict__ o4,
         const float* __restrict__ wt, const float* __restrict__ bias,
         float* __restrict__ out) {
    const int tx = threadIdx.x, ty = threadIdx.y;
    const int tid = ty * 32 + tx;
    const int b   = blockIdx.z;
    const int px  = blockIdx.x * 32 + tx;
    const int py  = blockIdx.y * 4 + ty;
    const int p   = py * WW + px;

    __shared__ __align__(16) u64 s_w[8 * 9 * 32];

    u64 acc[32];
#pragma unroll
    for (int q = 0; q < 32; q++) acc[q] = 0ull;

    const float* xb = x + (size_t)b * CIN * HWSZ;
    const float* ob = o4 + (size_t)b * OC4 * HWSZ;

    for (int g = 0; g < DG; g++) {
        __syncthreads();
        const u64* wg = (const u64*)(wt + (size_t)g * 8 * 9 * 64);
        for (int i = tid; i < 8 * 9 * 32; i += 128) s_w[i] = wg[i];
        __syncthreads();

        const float* xg = xb + (size_t)g * 8 * HWSZ;

        for (int k = 0; k < KK; k++) {
            float dy = 10.f * fast_tanh(ob[(size_t)(g * 18 + 2 * k) * HWSZ + p]);
            float dx = 10.f * fast_tanh(ob[(size_t)(g * 18 + 2 * k + 1) * HWSZ + p]);
            float m  = fast_sigmoid(ob[(size_t)(288 + g * 9 + k) * HWSZ + p]);

            float fy = (float)py - 1.f + (float)(k / 3) + dy;
            float fx = (float)px - 1.f + (float)(k % 3) + dx;
            float y0f = floorf(fy), x0f = floorf(fx);
            float ly = fy - y0f, lx = fx - x0f;
            int y0 = (int)y0f, x0 = (int)x0f;
            int y1 = y0 + 1, x1 = x0 + 1;

            bool vy0 = (y0 >= 0) && (y0 < HH);
            bool vy1 = (y1 >= 0) && (y1 < HH);
            bool vx0 = (x0 >= 0) && (x0 < WW);
            bool vx1 = (x1 >= 0) && (x1 < WW);

            float w00 = (1.f - ly) * (1.f - lx) * ((vy0 && vx0) ? m : 0.f);
            float w01 = (1.f - ly) * lx         * ((vy0 && vx1) ? m : 0.f);
            float w10 = ly * (1.f - lx)         * ((vy1 && vx0) ? m : 0.f);
            float w11 = ly * lx                 * ((vy1 && vx1) ? m : 0.f);

            int yc0 = min(max(y0, 0), HH - 1);
            int yc1 = min(max(y1, 0), HH - 1);
            int xc0 = min(max(x0, 0), WW - 1);
            int xc1 = min(max(x1, 0), WW - 1);
            int i00 = yc0 * WW + xc0, i01 = yc0 * WW + xc1;
            int i10 = yc1 * WW + xc0, i11 = yc1 * WW + xc1;

#pragma unroll
            for (int c = 0; c < 8; c++) {
                const float* xc = xg + (size_t)c * HWSZ;
                float v = w00 * xc[i00] + w01 * xc[i01] + w10 * xc[i10] + w11 * xc[i11];
                u64 v2 = pk2(v, v);
                const ulonglong2* wp = (const ulonglong2*)&s_w[(c * 9 + k) * 32];
#pragma unroll
                for (int q = 0; q < 16; q++) {
                    ulonglong2 wq = wp[q];
                    acc[q * 2 + 0] = ffma2(v2, wq.x, acc[q * 2 + 0]);
                    acc[q * 2 + 1] = ffma2(v2, wq.y, acc[q * 2 + 1]);
                }
            }
        }
    }

    float* outb = out + (size_t)b * COUT * HWSZ + p;
#pragma unroll
    for (int q = 0; q < 32; q++) {
        float2 v = upk(acc[q]);
        outb[(size_t)(2 * q + 0) * HWSZ] = v.x + bias[2 * q + 0];
        outb[(size_t)(2 * q + 1) * HWSZ] = v.y + bias[2 * q + 1];
    }
}

// ---------------------------------------------------------------------------
// Launcher
// ---------------------------------------------------------------------------
extern "C" void kernel_launch(void* const* d_in, const int* in_sizes, int n_in,
                              void* d_out, int out_size) {
    const float* x          = (const float*)d_in[0];
    const float* extra_feat = (const float*)d_in[1];
    const float* w1 = (const float*)d_in[2];
    const float* b1 = (const float*)d_in[3];
    const float* w2 = (const float*)d_in[4];
    const float* b2 = (const float*)d_in[5];
    const float* w3 = (const float*)d_in[6];
    const float* b3 = (const float*)d_in[7];
    const float* w4 = (const float*)d_in[8];
    const float* b4 = (const float*)d_in[9];
    const float* weight = (const float*)d_in[10];
    const float* bias   = (const float*)d_in[11];
    float* out = (float*)d_out;

    float *t1, *t2, *o4, *wt;
    __nv_bfloat16 *axh, *axl, *uh, *ul;
    __nv_bfloat16 *w1h, *w1l, *w2h, *w2l, *w3h, *w3l, *w4h, *w4l;
    cudaGetSymbolAddress((void**)&t1, g_t1);
    cudaGetSymbolAddress((void**)&t2, g_t2);
    cudaGetSymbolAddress((void**)&o4, g_o4);
    cudaGetSymbolAddress((void**)&wt, g_wt);
    cudaGetSymbolAddress((void**)&axh, g_axh);
    cudaGetSymbolAddress((void**)&axl, g_axl);
    cudaGetSymbolAddress((void**)&uh, g_uh);
    cudaGetSymbolAddress((void**)&ul, g_ul);
    cudaGetSymbolAddress((void**)&w1h, g_w1h);
    cudaGetSymbolAddress((void**)&w1l, g_w1l);
    cudaGetSymbolAddress((void**)&w2h, g_w2h);
    cudaGetSymbolAddress((void**)&w2l, g_w2l);
    cudaGetSymbolAddress((void**)&w3h, g_w3h);
    cudaGetSymbolAddress((void**)&w3l, g_w3l);
    cudaGetSymbolAddress((void**)&w4h, g_w4h);
    cudaGetSymbolAddress((void**)&w4l, g_w4l);

    cudaFuncSetAttribute(conv_mma_k, cudaFuncAttributeMaxDynamicSharedMemorySize, SMEMC);
    cudaFuncSetAttribute(conv_mma_pre_k, cudaFuncAttributeMaxDynamicSharedMemorySize, SMEMC);

    // prep: deform weight transpose, conv weight splits, extra_feat convert
    {
        int n = CIN * KK * COUT;
        transpose_weight_k<<<(n + 255) / 256, 256>>>(weight, wt);
        int n1 = 9 * 64 * 192;
        split_w_k<<<(n1 + 255) / 256, 256>>>(w1, w1h, w1l, 64, 64, 192);
        int n2 = 9 * 64 * 64;
        split_w_k<<<(n2 + 255) / 256, 256>>>(w2, w2h, w2l, 64, 64, 64);
        split_w_k<<<(n2 + 255) / 256, 256>>>(w3, w3h, w3l, 64, 64, 64);
        int n4 = 9 * OCP4 * 64;
        split_w_k<<<(n4 + 255) / 256, 256>>>(w4, w4h, w4l, OC4, OCP4, 64);
        convert_k<<<dim3(HH, BATCH), 256>>>(extra_feat, axh, axl, 192);
    }

    // conv1 (pre-split input): ax (192ch) -> t1 float, lrelu
    conv_mma_pre_k<<<dim3(HH, 1, BATCH), 256, SMEMC>>>(axh, axl, w1h, w1l, b1, t1,
                                                       192, 64, 64, 1);
    // conv2 (R13 path): t1 -> t2, lrelu
    conv_mma_k<<<dim3(HH, 1, BATCH), 256, SMEMC>>>(t1, w2h, w2l, b2, t2, 64, 64, 64, 1);
    // conv3 (R13 path): t2 -> t1, lrelu
    conv_mma_k<<<dim3(HH, 1, BATCH), 256, SMEMC>>>(t2, w3h, w3l, b3, t1, 64, 64, 64, 1);
    // convert t1 -> pre-split pair for conv4
    convert_k<<<dim3(HH, BATCH), 256>>>(t1, uh, ul, 64);
    // conv4 (pre-split input): u -> o4 (432ch float, +bias, no activation)
    conv_mma_pre_k<<<dim3(HH, OCP4 / 64, BATCH), 256, SMEMC>>>(uh, ul, w4h, w4l, b4, o4,
                                                               64, OCP4, OC4, 0);
    // deformable conv: x + o4 -> out
    deform_k<<<dim3(WW / 32, HH / 4, BATCH), dim3(32, 4)>>>(x, o4, wt, bias, out);
}

// round 16
// speedup vs baseline: 1.5741x; 1.0654x over previous
#include <cuda_runtime.h>
#include <cuda_bf16.h>
#include <math.h>
#include <stdint.h>

// Problem constants
constexpr int BATCH = 4;
constexpr int CIN   = 128;
constexpr int COUT  = 64;
constexpr int HH    = 128;
constexpr int WW    = 128;
constexpr int HWSZ  = HH * WW;
constexpr int DG    = 16;
constexpr int KK    = 9;
constexpr int OC4   = 27 * DG;   // 432
constexpr int OCP4  = 448;       // padded oc for conv4 MMA (28 x 16)

// Scratch (static device buffers; allocation APIs are forbidden)
__device__ float g_t1[(size_t)BATCH * COUT * HWSZ];
__device__ float g_t2[(size_t)BATCH * COUT * HWSZ];
__device__ float g_o4[(size_t)BATCH * OC4 * HWSZ];
__device__ __align__(16) float g_wt[(size_t)CIN * KK * COUT];        // deform weight [cin][k][o]
// pre-split activations [b][y][px][cin] bf16 hi/lo
__device__ __align__(16) __nv_bfloat16 g_axh[(size_t)BATCH * HWSZ * 192];
__device__ __align__(16) __nv_bfloat16 g_axl[(size_t)BATCH * HWSZ * 192];
__device__ __align__(16) __nv_bfloat16 g_uh[(size_t)BATCH * HWSZ * 64];
__device__ __align__(16) __nv_bfloat16 g_ul[(size_t)BATCH * HWSZ * 64];
// conv weights [k][ocp][cin] split bf16
__device__ __align__(16) __nv_bfloat16 g_w1h[(size_t)9 * 64 * 192];
__device__ __align__(16) __nv_bfloat16 g_w1l[(size_t)9 * 64 * 192];
__device__ __align__(16) __nv_bfloat16 g_w2h[(size_t)9 * 64 * 64];
__device__ __align__(16) __nv_bfloat16 g_w2l[(size_t)9 * 64 * 64];
__device__ __align__(16) __nv_bfloat16 g_w3h[(size_t)9 * 64 * 64];
__device__ __align__(16) __nv_bfloat16 g_w3l[(size_t)9 * 64 * 64];
__device__ __align__(16) __nv_bfloat16 g_w4h[(size_t)9 * OCP4 * 64];
__device__ __align__(16) __nv_bfloat16 g_w4l[(size_t)9 * OCP4 * 64];

// ---------------------------------------------------------------------------
// Helpers
// ---------------------------------------------------------------------------
typedef unsigned long long u64;

__device__ __forceinline__ u64 ffma2(u64 a, u64 b, u64 c) {
    u64 d;
    asm("fma.rn.f32x2 %0, %1, %2, %3;" : "=l"(d) : "l"(a), "l"(b), "l"(c));
    return d;
}
__device__ __forceinline__ u64 pk2(float lo, float hi) {
    u64 r;
    asm("mov.b64 %0, {%1, %2};" : "=l"(r) : "f"(lo), "f"(hi));
    return r;
}
__device__ __forceinline__ float2 upk(u64 v) {
    float2 r;
    asm("mov.b64 {%0, %1}, %2;" : "=f"(r.x), "=f"(r.y) : "l"(v));
    return r;
}
__device__ __forceinline__ float fast_tanh(float x) {
    return 1.f - 2.f / (__expf(2.f * x) + 1.f);
}
__device__ __forceinline__ float fast_sigmoid(float x) {
    return 1.f / (1.f + __expf(-x));
}
__device__ __forceinline__ uint32_t smem_u32(const void* p) {
    uint32_t a;
    asm("{ .reg .u64 t; cvta.to.shared.u64 t, %1; cvt.u32.u64 %0, t; }" : "=r"(a) : "l"(p));
    return a;
}
__device__ __forceinline__ void ldsm_x4(uint32_t& r0, uint32_t& r1,
                                        uint32_t& r2, uint32_t& r3, uint32_t addr) {
    asm volatile("ldmatrix.sync.aligned.m8n8.x4.shared.b16 {%0,%1,%2,%3}, [%4];"
                 : "=r"(r0), "=r"(r1), "=r"(r2), "=r"(r3) : "r"(addr));
}
__device__ __forceinline__ void mma16816(float* d, const uint32_t* a,
                                         uint32_t b0, uint32_t b1) {
    asm volatile(
        "mma.sync.aligned.m16n8k16.row.col.f32.bf16.bf16.f32 "
        "{%0,%1,%2,%3}, {%4,%5,%6,%7}, {%8,%9}, {%0,%1,%2,%3};"
        : "+f"(d[0]), "+f"(d[1]), "+f"(d[2]), "+f"(d[3])
        : "r"(a[0]), "r"(a[1]), "r"(a[2]), "r"(a[3]), "r"(b0), "r"(b1));
}
#define CP16(dst, src) asm volatile("cp.async.cg.shared.global [%0], [%1], 16;" :: "r"(dst), "l"(src))
#define CP_COMMIT()    asm volatile("cp.async.commit_group;" ::: "memory")
#define CP_WAIT0()     asm volatile("cp.async.wait_group 0;" ::: "memory")

// ---------------------------------------------------------------------------
// Merged prep kernel: deform-weight transpose + 4 conv-weight bf16 splits
// ---------------------------------------------------------------------------
__device__ __forceinline__ void split_one(const float* w, __nv_bfloat16* h,
                                          __nv_bfloat16* l, int idx,
                                          int Cout_real, int ocp, int Cin) {
    int c  = idx % Cin;
    int oc = (idx / Cin) % ocp;
    int k  = idx / (Cin * ocp);
    float v = (oc < Cout_real) ? w[((size_t)oc * Cin + c) * 9 + k] : 0.f;
    __nv_bfloat16 hi = __float2bfloat16(v);
    float hf = __bfloat162float(hi);
    h[idx] = hi;
    l[idx] = __float2bfloat16(v - hf);
}

constexpr int PN0 = CIN * KK * COUT;        // 73728 (wt)
constexpr int PN1 = 9 * 64 * 192;           // 110592
constexpr int PN2 = 9 * 64 * 64;            // 36864
constexpr int PN4 = 9 * OCP4 * 64;          // 258048
constexpr int PTOT = PN0 + PN1 + 2 * PN2 + PN4;  // 516096

__global__ void prep_k(const float* __restrict__ dw, float* __restrict__ wt,
                       const float* __restrict__ w1, const float* __restrict__ w2,
                       const float* __restrict__ w3, const float* __restrict__ w4) {
    int idx = blockIdx.x * blockDim.x + threadIdx.x;
    if (idx >= PTOT) return;
    if (idx < PN0) {
        int o   = idx % COUT;
        int k   = (idx / COUT) % KK;
        int cin = idx / (COUT * KK);
        wt[idx] = dw[((size_t)o * CIN + cin) * KK + k];
        return;
    }
    idx -= PN0;
    if (idx < PN1) { split_one(w1, g_w1h, g_w1l, idx, 64, 64, 192); return; }
    idx -= PN1;
    if (idx < PN2) { split_one(w2, g_w2h, g_w2l, idx, 64, 64, 64); return; }
    idx -= PN2;
    if (idx < PN2) { split_one(w3, g_w3h, g_w3l, idx, 64, 64, 64); return; }
    idx -= PN2;
    split_one(w4, g_w4h, g_w4l, idx, OC4, OCP4, 64);
}

// Convert float NCHW -> [b][y][px][Cin] bf16 hi/lo. grid (HH, BATCH), 256 thr.
__global__ void __launch_bounds__(256)
convert_k(const float* __restrict__ in, __nv_bfloat16* __restrict__ oh,
          __nv_bfloat16* __restrict__ ol, int Cin) {
    __shared__ __nv_bfloat16 sh[128][40];
    __shared__ __nv_bfloat16 sl[128][40];
    const int tid  = threadIdx.x;
    const int wid  = tid >> 5;
    const int lane = tid & 31;
    const int y = blockIdx.x;
    const int b = blockIdx.y;
    const int nct = Cin >> 5;

    for (int ct = 0; ct < nct; ct++) {
        __syncthreads();
        for (int r = 0; r < 4; r++) {
            int c = ct * 32 + r * 8 + wid;
            const float4* src = (const float4*)(in + ((size_t)b * Cin + c) * HWSZ + (size_t)y * WW);
            float4 v = src[lane];
            int px = lane * 4;
            float vv[4] = {v.x, v.y, v.z, v.w};
#pragma unroll
            for (int j = 0; j < 4; j++) {
                __nv_bfloat16 h = __float2bfloat16(vv[j]);
                float hf = __bfloat162float(h);
                sh[px + j][r * 8 + wid] = h;
                sl[px + j][r * 8 + wid] = __float2bfloat16(vv[j] - hf);
            }
        }
        __syncthreads();
        for (int i = tid; i < 512; i += 256) {
            int px = i >> 2, cc = (i & 3) * 8;
            size_t dst = ((size_t)(b * HWSZ + y * WW + px)) * Cin + ct * 32 + cc;
            *(uint4*)(oh + dst) = *(uint4*)&sh[px][cc];
            *(uint4*)(ol + dst) = *(uint4*)&sl[px][cc];
        }
    }
}

// ---------------------------------------------------------------------------
// Shared smem layout for conv kernels
// ---------------------------------------------------------------------------
constexpr int LDX = 72;
constexpr int LDW = 72;
constexpr uint32_t SX_H = 0;
constexpr uint32_t SX_L = SX_H + 130 * LDX * 2;        // 18720
constexpr uint32_t SW_H = SX_L + 130 * LDX * 2;        // 37440
constexpr uint32_t SW_L = SW_H + 3 * 64 * LDW * 2;     // 65088
constexpr uint32_t SMEMC = SW_L + 3 * 64 * LDW * 2 + 64; // 92800

// ---------------------------------------------------------------------------
// MMA core (shared by all conv kernels): runs after sx/sw are staged.
// ---------------------------------------------------------------------------
__device__ __forceinline__ void conv_mma_core(
    uint32_t sbase, float (*d)[4],
    int a_rl, int a_ko, int b_r, int b_ko, int b_seg, int w_px) {
#pragma unroll
    for (int djs = 0; djs < 3; djs++) {
#pragma unroll
        for (int kc = 0; kc < 4; kc++) {
            uint32_t aH[4], aL[4];
            {
                uint32_t off = (uint32_t)((djs * 64 + a_rl) * LDW + kc * 16 + a_ko) * 2;
                ldsm_x4(aH[0], aH[1], aH[2], aH[3], sbase + SW_H + off);
                ldsm_x4(aL[0], aL[1], aL[2], aL[3], sbase + SW_L + off);
            }
#pragma unroll
            for (int nt2 = 0; nt2 < 4; nt2++) {
                const int row = djs + w_px * 64 + nt2 * 16 + b_seg * 8 + b_r;
                uint32_t off = (uint32_t)(row * LDX + kc * 16 + b_ko) * 2;
                uint32_t bh0, bh1, bh2, bh3, bl0, bl1, bl2, bl3;
                ldsm_x4(bh0, bh1, bh2, bh3, sbase + SX_H + off);
                ldsm_x4(bl0, bl1, bl2, bl3, sbase + SX_L + off);
                float* d0 = d[nt2 * 2];
                float* d1 = d[nt2 * 2 + 1];
                mma16816(d0, aH, bh0, bh1);
                mma16816(d0, aH, bl0, bl1);
                mma16816(d0, aL, bh0, bh1);
                mma16816(d1, aH, bh2, bh3);
                mma16816(d1, aH, bl2, bl3);
                mma16816(d1, aL, bh2, bh3);
            }
        }
    }
}

// stage weights (3 taps of one di) via cp.async
__device__ __forceinline__ void stage_w(
    uint32_t sbase, const __nv_bfloat16* wh, const __nv_bfloat16* wl,
    int tid, int di, int oc0, int sl, int Cin, int ocp) {
    for (int i = tid; i < 3 * 512; i += 256) {
        int t = i >> 9, r = i & 511;
        int ocl = r >> 3, cc = (r & 7) * 8;
        size_t gidx = ((size_t)((di + 1) * 3 + t) * ocp + oc0 + ocl) * Cin
                    + (size_t)sl * 64 + cc;
        uint32_t doff = (uint32_t)((t * 64 + ocl) * LDW + cc) * 2;
        CP16(sbase + SW_H + doff, wh + gidx);
        CP16(sbase + SW_L + doff, wl + gidx);
    }
}

// ---------------------------------------------------------------------------
// conv_mma_k — float input (in-kernel split staging), float/lrelu epilogue.
// Used for conv2.
// ---------------------------------------------------------------------------
__global__ void __launch_bounds__(256, 2)
conv_mma_k(const float* __restrict__ in,
           const __nv_bfloat16* __restrict__ wh, const __nv_bfloat16* __restrict__ wl,
           const float* __restrict__ bias, float* __restrict__ out,
           int Cin, int ocp, int Cout_real, int lrelu) {
    extern __shared__ char sm[];
    const uint32_t sbase = smem_u32(sm);

    const int tid  = threadIdx.x;
    const int w    = tid >> 5;
    const int lane = tid & 31;
    const int y = blockIdx.x;
    const int m = blockIdx.y;
    const int b = blockIdx.z;
    const int oc0  = m * 64;
    const int w_oc = w & 3;
    const int w_px = w >> 2;

    __nv_bfloat16* sxh = (__nv_bfloat16*)(sm + SX_H);
    __nv_bfloat16* sxl = (__nv_bfloat16*)(sm + SX_L);

    for (int i = tid; i < LDX; i += 256) {
        sxh[i] = __float2bfloat16(0.f);
        sxl[i] = __float2bfloat16(0.f);
        sxh[129 * LDX + i] = __float2bfloat16(0.f);
        sxl[129 * LDX + i] = __float2bfloat16(0.f);
    }

    float d[8][4];
#pragma unroll
    for (int nt = 0; nt < 8; nt++)
#pragma unroll
        for (int j = 0; j < 4; j++) d[nt][j] = 0.f;

    const float* inb = in + (size_t)b * Cin * HWSZ;

    const int a_rl = w_oc * 16 + (lane & 15);
    const int a_ko = (lane >> 4) * 8;
    const int b_r  = lane & 7;
    const int b_ko = ((lane >> 3) & 1) * 8;
    const int b_seg = lane >> 4;

    const int nslab = Cin >> 6;
    for (int sl = 0; sl < nslab; sl++) {
        for (int di = -1; di <= 1; di++) {
            __syncthreads();
            {
                const int yy = y + di;
                const bool valid = (yy >= 0) && (yy < HH);
                const float* trow = inb + ((size_t)sl * 64) * HWSZ + (size_t)(valid ? yy : 0) * WW;
                for (int i = tid; i < 64 * 128; i += 256) {
                    int c = i >> 7, px = i & 127;
                    float v = valid ? trow[(size_t)c * HWSZ + px] : 0.f;
                    __nv_bfloat16 h = __float2bfloat16(v);
                    float hf = __bfloat162float(h);
                    sxh[(1 + px) * LDX + c] = h;
                    sxl[(1 + px) * LDX + c] = __float2bfloat16(v - hf);
                }
            }
            stage_w(sbase, wh, wl, tid, di, oc0, sl, Cin, ocp);
            CP_COMMIT();
            CP_WAIT0();
            __syncthreads();
            conv_mma_core(sbase, d, a_rl, a_ko, b_r, b_ko, b_seg, w_px);
        }
    }

    const int g   = lane >> 2;
    const int tig = lane & 3;
#pragma unroll
    for (int nt = 0; nt < 8; nt++) {
        int px  = w_px * 64 + nt * 8 + tig * 2;
        int o0  = oc0 + w_oc * 16 + g;
        int o1  = o0 + 8;
        size_t rowoff = (size_t)y * WW + px;
        if (o0 < Cout_real) {
            float bv = bias[o0];
            float vx = d[nt][0] + bv, vy = d[nt][1] + bv;
            if (lrelu) {
                vx = (vx >= 0.f) ? vx : 0.1f * vx;
                vy = (vy >= 0.f) ? vy : 0.1f * vy;
            }
            *(float2*)(out + ((size_t)b * Cout_real + o0) * HWSZ + rowoff) = make_float2(vx, vy);
        }
        if (o1 < Cout_real) {
            float bv = bias[o1];
            float vx = d[nt][2] + bv, vy = d[nt][3] + bv;
            if (lrelu) {
                vx = (vx >= 0.f) ? vx : 0.1f * vx;
                vy = (vy >= 0.f) ? vy : 0.1f * vy;
            }
            *(float2*)(out + ((size_t)b * Cout_real + o1) * HWSZ + rowoff) = make_float2(vx, vy);
        }
    }
}

// ---------------------------------------------------------------------------
// conv_mma_out_pre_k — float input, bf16-PAIR output (pre-split for next conv).
// Used for conv3 only (writes uh/ul consumed by conv4). lrelu always on.
// ---------------------------------------------------------------------------
__global__ void __launch_bounds__(256, 2)
conv_mma_out_pre_k(const float* __restrict__ in,
                   const __nv_bfloat16* __restrict__ wh, const __nv_bfloat16* __restrict__ wl,
                   const float* __restrict__ bias,
                   __nv_bfloat16* __restrict__ outh, __nv_bfloat16* __restrict__ outl,
                   int Cin, int ocp) {
    extern __shared__ char sm[];
    const uint32_t sbase = smem_u32(sm);

    const int tid  = threadIdx.x;
    const int w    = tid >> 5;
    const int lane = tid & 31;
    const int y = blockIdx.x;
    const int b = blockIdx.z;
    const int oc0  = 0;
    const int w_oc = w & 3;
    const int w_px = w >> 2;

    __nv_bfloat16* sxh = (__nv_bfloat16*)(sm + SX_H);
    __nv_bfloat16* sxl = (__nv_bfloat16*)(sm + SX_L);

    for (int i = tid; i < LDX; i += 256) {
        sxh[i] = __float2bfloat16(0.f);
        sxl[i] = __float2bfloat16(0.f);
        sxh[129 * LDX + i] = __float2bfloat16(0.f);
        sxl[129 * LDX + i] = __float2bfloat16(0.f);
    }

    float d[8][4];
#pragma unroll
    for (int nt = 0; nt < 8; nt++)
#pragma unroll
        for (int j = 0; j < 4; j++) d[nt][j] = 0.f;

    const float* inb = in + (size_t)b * Cin * HWSZ;

    const int a_rl = w_oc * 16 + (lane & 15);
    const int a_ko = (lane >> 4) * 8;
    const int b_r  = lane & 7;
    const int b_ko = ((lane >> 3) & 1) * 8;
    const int b_seg = lane >> 4;

    for (int di = -1; di <= 1; di++) {
        __syncthreads();
        {
            const int yy = y + di;
            const bool valid = (yy >= 0) && (yy < HH);
            const float* trow = inb + (size_t)(valid ? yy : 0) * WW;
            for (int i = tid; i < 64 * 128; i += 256) {
                int c = i >> 7, px = i & 127;
                float v = valid ? trow[(size_t)c * HWSZ + px] : 0.f;
                __nv_bfloat16 h = __float2bfloat16(v);
                float hf = __bfloat162float(h);
                sxh[(1 + px) * LDX + c] = h;
                sxl[(1 + px) * LDX + c] = __float2bfloat16(v - hf);
            }
        }
        stage_w(sbase, wh, wl, tid, di, oc0, 0, Cin, ocp);
        CP_COMMIT();
        CP_WAIT0();
        __syncthreads();
        conv_mma_core(sbase, d, a_rl, a_ko, b_r, b_ko, b_seg, w_px);
    }

    // bf16-pair epilogue: bias+lrelu, split, smem transpose, coalesced store
    const int g   = lane >> 2;
    const int tig = lane & 3;
    __syncthreads();   // all MMA reads of sx done; reuse sx region
#pragma unroll
    for (int nt = 0; nt < 8; nt++) {
        int px = w_px * 64 + nt * 8 + tig * 2;
        int ol0 = w_oc * 16 + g;
        int ol1 = ol0 + 8;
        float bv0 = bias[ol0], bv1 = bias[ol1];
#pragma unroll
        for (int j = 0; j < 4; j++) {
            int ocl = (j < 2) ? ol0 : ol1;
            float v = d[nt][j] + ((j < 2) ? bv0 : bv1);
            v = (v >= 0.f) ? v : 0.1f * v;
            __nv_bfloat16 h = __float2bfloat16(v);
            float hf = __bfloat162float(h);
            int pxe = px + (j & 1);
            sxh[pxe * LDX + ocl] = h;
            sxl[pxe * LDX + ocl] = __float2bfloat16(v - hf);
        }
    }
    __syncthreads();
    for (int i = tid; i < 1024; i += 256) {
        int px = i >> 3, cc = (i & 7) * 8;
        size_t dst = ((size_t)(b * HH + y) * WW + px) * 64 + cc;
        *(uint4*)(outh + dst) = *(uint4*)&sxh[px * LDX + cc];
        *(uint4*)(outl + dst) = *(uint4*)&sxl[px * LDX + cc];
    }
}

// ---------------------------------------------------------------------------
// conv_mma_pre_k — pre-split bf16 input (cp.async copy staging), float epilogue.
// Used for conv1 (Cin=192) and conv4 (Cin=64, 7 oc-tiles).
// ---------------------------------------------------------------------------
__global__ void __launch_bounds__(256, 2)
conv_mma_pre_k(const __nv_bfloat16* __restrict__ xh, const __nv_bfloat16* __restrict__ xl,
               const __nv_bfloat16* __restrict__ wh, const __nv_bfloat16* __restrict__ wl,
               const float* __restrict__ bias, float* __restrict__ out,
               int Cin, int ocp, int Cout_real, int lrelu) {
    extern __shared__ char sm[];
    const uint32_t sbase = smem_u32(sm);

    const int tid  = threadIdx.x;
    const int w    = tid >> 5;
    const int lane = tid & 31;
    const int y = blockIdx.x;
    const int m = blockIdx.y;
    const int b = blockIdx.z;
    const int oc0  = m * 64;
    const int w_oc = w & 3;
    const int w_px = w >> 2;

    __nv_bfloat16* sxh = (__nv_bfloat16*)(sm + SX_H);
    __nv_bfloat16* sxl = (__nv_bfloat16*)(sm + SX_L);

    for (int i = tid; i < LDX; i += 256) {
        sxh[i] = __float2bfloat16(0.f);
        sxl[i] = __float2bfloat16(0.f);
        sxh[129 * LDX + i] = __float2bfloat16(0.f);
        sxl[129 * LDX + i] = __float2bfloat16(0.f);
    }

    float d[8][4];
#pragma unroll
    for (int nt = 0; nt < 8; nt++)
#pragma unroll
        for (int j = 0; j < 4; j++) d[nt][j] = 0.f;

    const int a_rl = w_oc * 16 + (lane & 15);
    const int a_ko = (lane >> 4) * 8;
    const int b_r  = lane & 7;
    const int b_ko = ((lane >> 3) & 1) * 8;
    const int b_seg = lane >> 4;

    const int nslab = Cin >> 6;
    for (int sl = 0; sl < nslab; sl++) {
        for (int di = -1; di <= 1; di++) {
            __syncthreads();
            // x staging via cp.async (copy-only)
            {
                const int yy = y + di;
                const bool valid = (yy >= 0) && (yy < HH);
                if (valid) {
                    const size_t rowbase = ((size_t)(b * HH + yy) * WW) * Cin + sl * 64;
                    for (int i = tid; i < 1024; i += 256) {
                        int px = i >> 3, cc = (i & 7) * 8;
                        size_t src = rowbase + (size_t)px * Cin + cc;
                        uint32_t off = (uint32_t)((1 + px) * LDX + cc) * 2;
                        CP16(sbase + SX_H + off, xh + src);
                        CP16(sbase + SX_L + off, xl + src);
                    }
                } else {
                    const uint4 z = make_uint4(0, 0, 0, 0);
                    for (int i = tid; i < 1024; i += 256) {
                        int px = i >> 3, cc = (i & 7) * 8;
                        uint32_t off = (uint32_t)((1 + px) * LDX + cc) * 2;
                        *(uint4*)(sm + SX_H + off) = z;
                        *(uint4*)(sm + SX_L + off) = z;
                    }
                }
            }
            stage_w(sbase, wh, wl, tid, di, oc0, sl, Cin, ocp);
            CP_COMMIT();
            CP_WAIT0();
            __syncthreads();
            conv_mma_core(sbase, d, a_rl, a_ko, b_r, b_ko, b_seg, w_px);
        }
    }

    const int g   = lane >> 2;
    const int tig = lane & 3;
#pragma unroll
    for (int nt = 0; nt < 8; nt++) {
        int px  = w_px * 64 + nt * 8 + tig * 2;
        int o0  = oc0 + w_oc * 16 + g;
        int o1  = o0 + 8;
        size_t rowoff = (size_t)y * WW + px;
        if (o0 < Cout_real) {
            float bv = bias[o0];
            float vx = d[nt][0] + bv, vy = d[nt][1] + bv;
            if (lrelu) {
                vx = (vx >= 0.f) ? vx : 0.1f * vx;
                vy = (vy >= 0.f) ? vy : 0.1f * vy;
            }
            *(float2*)(out + ((size_t)b * Cout_real + o0) * HWSZ + rowoff) = make_float2(vx, vy);
        }
        if (o1 < Cout_real) {
            float bv = bias[o1];
            float vx = d[nt][2] + bv, vy = d[nt][3] + bv;
            if (lrelu) {
                vx = (vx >= 0.f) ? vx : 0.1f * vx;
                vy = (vy >= 0.f) ? vy : 0.1f * vy;
            }
            *(float2*)(out + ((size_t)b * Cout_real + o1) * HWSZ + rowoff) = make_float2(vx, vy);
        }
    }
}

// ---------------------------------------------------------------------------
// Deformable conv — R4 best version (+ fast activations, verified neutral).
// ---------------------------------------------------------------------------
__global__ void __launch_bounds__(128, 4)
deform_k(const float* __restrict__ x, const float* __restrict__ o4,
         const float* __restrict__ wt, const float* __restrict__ bias,
         float* __restrict__ out) {
    const int tx = threadIdx.x, ty = threadIdx.y;
    const int tid = ty * 32 + tx;
    const int b   = blockIdx.z;
    const int px  = blockIdx.x * 32 + tx;
    const int py  = blockIdx.y * 4 + ty;
    const int p   = py * WW + px;

    __shared__ __align__(16) u64 s_w[8 * 9 * 32];

    u64 acc[32];
#pragma unroll
    for (int q = 0; q < 32; q++) acc[q] = 0ull;

    const float* xb = x + (size_t)b * CIN * HWSZ;
    const float* ob = o4 + (size_t)b * OC4 * HWSZ;

    for (int g = 0; g < DG; g++) {
        __syncthreads();
        const u64* wg = (const u64*)(wt + (size_t)g * 8 * 9 * 64);
        for (int i = tid; i < 8 * 9 * 32; i += 128) s_w[i] = wg[i];
        __syncthreads();

        const float* xg = xb + (size_t)g * 8 * HWSZ;

        for (int k = 0; k < KK; k++) {
            float dy = 10.f * fast_tanh(ob[(size_t)(g * 18 + 2 * k) * HWSZ + p]);
            float dx = 10.f * fast_tanh(ob[(size_t)(g * 18 + 2 * k + 1) * HWSZ + p]);
            float m  = fast_sigmoid(ob[(size_t)(288 + g * 9 + k) * HWSZ + p]);

            float fy = (float)py - 1.f + (float)(k / 3) + dy;
            float fx = (float)px - 1.f + (float)(k % 3) + dx;
            float y0f = floorf(fy), x0f = floorf(fx);
            float ly = fy - y0f, lx = fx - x0f;
            int y0 = (int)y0f, x0 = (int)x0f;
            int y1 = y0 + 1, x1 = x0 + 1;

            bool vy0 = (y0 >= 0) && (y0 < HH);
            bool vy1 = (y1 >= 0) && (y1 < HH);
            bool vx0 = (x0 >= 0) && (x0 < WW);
            bool vx1 = (x1 >= 0) && (x1 < WW);

            float w00 = (1.f - ly) * (1.f - lx) * ((vy0 && vx0) ? m : 0.f);
            float w01 = (1.f - ly) * lx         * ((vy0 && vx1) ? m : 0.f);
            float w10 = ly * (1.f - lx)         * ((vy1 && vx0) ? m : 0.f);
            float w11 = ly * lx                 * ((vy1 && vx1) ? m : 0.f);

            int yc0 = min(max(y0, 0), HH - 1);
            int yc1 = min(max(y1, 0), HH - 1);
            int xc0 = min(max(x0, 0), WW - 1);
            int xc1 = min(max(x1, 0), WW - 1);
            int i00 = yc0 * WW + xc0, i01 = yc0 * WW + xc1;
            int i10 = yc1 * WW + xc0, i11 = yc1 * WW + xc1;

#pragma unroll
            for (int c = 0; c < 8; c++) {
                const float* xc = xg + (size_t)c * HWSZ;
                float v = w00 * xc[i00] + w01 * xc[i01] + w10 * xc[i10] + w11 * xc[i11];
                u64 v2 = pk2(v, v);
                const ulonglong2* wp = (const ulonglong2*)&s_w[(c * 9 + k) * 32];
#pragma unroll
                for (int q = 0; q < 16; q++) {
                    ulonglong2 wq = wp[q];
                    acc[q * 2 + 0] = ffma2(v2, wq.x, acc[q * 2 + 0]);
                    acc[q * 2 + 1] = ffma2(v2, wq.y, acc[q * 2 + 1]);
                }
            }
        }
    }

    float* outb = out + (size_t)b * COUT * HWSZ + p;
#pragma unroll
    for (int q = 0; q < 32; q++) {
        float2 v = upk(acc[q]);
        outb[(size_t)(2 * q + 0) * HWSZ] = v.x + bias[2 * q + 0];
        outb[(size_t)(2 * q + 1) * HWSZ] = v.y + bias[2 * q + 1];
    }
}

// ---------------------------------------------------------------------------
// Launcher (launch order puts conv4 at position 6 for the ncu -s 5 capture)
// ---------------------------------------------------------------------------
extern "C" void kernel_launch(void* const* d_in, const int* in_sizes, int n_in,
                              void* d_out, int out_size) {
    const float* x          = (const float*)d_in[0];
    const float* extra_feat = (const float*)d_in[1];
    const float* w1 = (const float*)d_in[2];
    const float* b1 = (const float*)d_in[3];
    const float* w2 = (const float*)d_in[4];
    const float* b2 = (const float*)d_in[5];
    const float* w3 = (const float*)d_in[6];
    const float* b3 = (const float*)d_in[7];
    const float* w4 = (const float*)d_in[8];
    const float* b4 = (const float*)d_in[9];
    const float* weight = (const float*)d_in[10];
    const float* bias   = (const float*)d_in[11];
    float* out = (float*)d_out;

    float *t1, *t2, *o4, *wt;
    __nv_bfloat16 *axh, *axl, *uh, *ul;
    __nv_bfloat16 *w1h, *w1l, *w2h, *w2l, *w3h, *w3l, *w4h, *w4l;
    cudaGetSymbolAddress((void**)&t1, g_t1);
    cudaGetSymbolAddress((void**)&t2, g_t2);
    cudaGetSymbolAddress((void**)&o4, g_o4);
    cudaGetSymbolAddress((void**)&wt, g_wt);
    cudaGetSymbolAddress((void**)&axh, g_axh);
    cudaGetSymbolAddress((void**)&axl, g_axl);
    cudaGetSymbolAddress((void**)&uh, g_uh);
    cudaGetSymbolAddress((void**)&ul, g_ul);
    cudaGetSymbolAddress((void**)&w1h, g_w1h);
    cudaGetSymbolAddress((void**)&w1l, g_w1l);
    cudaGetSymbolAddress((void**)&w2h, g_w2h);
    cudaGetSymbolAddress((void**)&w2l, g_w2l);
    cudaGetSymbolAddress((void**)&w3h, g_w3h);
    cudaGetSymbolAddress((void**)&w3l, g_w3l);
    cudaGetSymbolAddress((void**)&w4h, g_w4h);
    cudaGetSymbolAddress((void**)&w4l, g_w4l);

    cudaFuncSetAttribute(conv_mma_k, cudaFuncAttributeMaxDynamicSharedMemorySize, SMEMC);
    cudaFuncSetAttribute(conv_mma_pre_k, cudaFuncAttributeMaxDynamicSharedMemorySize, SMEMC);
    cudaFuncSetAttribute(conv_mma_out_pre_k, cudaFuncAttributeMaxDynamicSharedMemorySize, SMEMC);

    // 1: merged prep (deform-weight transpose + all conv weight splits)
    prep_k<<<(PTOT + 255) / 256, 256>>>(weight, wt, w1, w2, w3, w4);
    // 2: extra_feat -> pre-split pair
    convert_k<<<dim3(HH, BATCH), 256>>>(extra_feat, axh, axl, 192);
    // 3: conv1 (pre-split input): ax (192ch) -> t1 float, lrelu
    conv_mma_pre_k<<<dim3(HH, 1, BATCH), 256, SMEMC>>>(axh, axl, w1h, w1l, b1, t1,
                                                       192, 64, 64, 1);
    // 4: conv2: t1 -> t2, lrelu
    conv_mma_k<<<dim3(HH, 1, BATCH), 256, SMEMC>>>(t1, w2h, w2l, b2, t2, 64, 64, 64, 1);
    // 5: conv3: t2 -> u (pre-split pair), lrelu
    conv_mma_out_pre_k<<<dim3(HH, 1, BATCH), 256, SMEMC>>>(t2, w3h, w3l, b3, uh, ul, 64, 64);
    // 6: conv4 (pre-split input): u -> o4 (432ch float, +bias) [ncu capture target]
    conv_mma_pre_k<<<dim3(HH, OCP4 / 64, BATCH), 256, SMEMC>>>(uh, ul, w4h, w4l, b4, o4,
                                                               64, OCP4, OC4, 0);
    // 7: deformable conv: x + o4 -> out
    deform_k<<<dim3(WW / 32, HH / 4, BATCH), dim3(32, 4)>>>(x, o4, wt, bias, out);
}

// round 17
// speedup vs baseline: 1.5797x; 1.0036x over previous
#include <cuda_runtime.h>
#include <cuda_bf16.h>
#include <math.h>
#include <stdint.h>

// Problem constants
constexpr int BATCH = 4;
constexpr int CIN   = 128;
constexpr int COUT  = 64;
constexpr int HH    = 128;
constexpr int WW    = 128;
constexpr int HWSZ  = HH * WW;
constexpr int DG    = 16;
constexpr int KK    = 9;
constexpr int OC4   = 27 * DG;   // 432
constexpr int OCP4  = 448;       // padded oc for conv4 MMA (28 x 16)

// Scratch (static device buffers; allocation APIs are forbidden)
__device__ float g_o4[(size_t)BATCH * OC4 * HWSZ];
__device__ __align__(16) float g_wt[(size_t)CIN * KK * COUT];        // deform weight [cin][k][o]
// pre-split activations [b][y][px][cin] bf16 hi/lo
__device__ __align__(16) __nv_bfloat16 g_axh[(size_t)BATCH * HWSZ * 192];
__device__ __align__(16) __nv_bfloat16 g_axl[(size_t)BATCH * HWSZ * 192];
__device__ __align__(16) __nv_bfloat16 g_p1h[(size_t)BATCH * HWSZ * 64];
__device__ __align__(16) __nv_bfloat16 g_p1l[(size_t)BATCH * HWSZ * 64];
__device__ __align__(16) __nv_bfloat16 g_p2h[(size_t)BATCH * HWSZ * 64];
__device__ __align__(16) __nv_bfloat16 g_p2l[(size_t)BATCH * HWSZ * 64];
// conv weights [k][ocp][cin] split bf16
__device__ __align__(16) __nv_bfloat16 g_w1h[(size_t)9 * 64 * 192];
__device__ __align__(16) __nv_bfloat16 g_w1l[(size_t)9 * 64 * 192];
__device__ __align__(16) __nv_bfloat16 g_w2h[(size_t)9 * 64 * 64];
__device__ __align__(16) __nv_bfloat16 g_w2l[(size_t)9 * 64 * 64];
__device__ __align__(16) __nv_bfloat16 g_w3h[(size_t)9 * 64 * 64];
__device__ __align__(16) __nv_bfloat16 g_w3l[(size_t)9 * 64 * 64];
__device__ __align__(16) __nv_bfloat16 g_w4h[(size_t)9 * OCP4 * 64];
__device__ __align__(16) __nv_bfloat16 g_w4l[(size_t)9 * OCP4 * 64];

// ---------------------------------------------------------------------------
// Helpers
// ---------------------------------------------------------------------------
typedef unsigned long long u64;

__device__ __forceinline__ u64 ffma2(u64 a, u64 b, u64 c) {
    u64 d;
    asm("fma.rn.f32x2 %0, %1, %2, %3;" : "=l"(d) : "l"(a), "l"(b), "l"(c));
    return d;
}
__device__ __forceinline__ u64 pk2(float lo, float hi) {
    u64 r;
    asm("mov.b64 %0, {%1, %2};" : "=l"(r) : "f"(lo), "f"(hi));
    return r;
}
__device__ __forceinline__ float2 upk(u64 v) {
    float2 r;
    asm("mov.b64 {%0, %1}, %2;" : "=f"(r.x), "=f"(r.y) : "l"(v));
    return r;
}
__device__ __forceinline__ float fast_tanh(float x) {
    return 1.f - 2.f / (__expf(2.f * x) + 1.f);
}
__device__ __forceinline__ float fast_sigmoid(float x) {
    return 1.f / (1.f + __expf(-x));
}
__device__ __forceinline__ uint32_t smem_u32(const void* p) {
    uint32_t a;
    asm("{ .reg .u64 t; cvta.to.shared.u64 t, %1; cvt.u32.u64 %0, t; }" : "=r"(a) : "l"(p));
    return a;
}
__device__ __forceinline__ void ldsm_x4(uint32_t& r0, uint32_t& r1,
                                        uint32_t& r2, uint32_t& r3, uint32_t addr) {
    asm volatile("ldmatrix.sync.aligned.m8n8.x4.shared.b16 {%0,%1,%2,%3}, [%4];"
                 : "=r"(r0), "=r"(r1), "=r"(r2), "=r"(r3) : "r"(addr));
}
__device__ __forceinline__ void mma16816(float* d, const uint32_t* a,
                                         uint32_t b0, uint32_t b1) {
    asm volatile(
        "mma.sync.aligned.m16n8k16.row.col.f32.bf16.bf16.f32 "
        "{%0,%1,%2,%3}, {%4,%5,%6,%7}, {%8,%9}, {%0,%1,%2,%3};"
        : "+f"(d[0]), "+f"(d[1]), "+f"(d[2]), "+f"(d[3])
        : "r"(a[0]), "r"(a[1]), "r"(a[2]), "r"(a[3]), "r"(b0), "r"(b1));
}
#define CP16(dst, src) asm volatile("cp.async.cg.shared.global [%0], [%1], 16;" :: "r"(dst), "l"(src))
#define CP_COMMIT()    asm volatile("cp.async.commit_group;" ::: "memory")
#define CP_WAIT0()     asm volatile("cp.async.wait_group 0;" ::: "memory")

// ---------------------------------------------------------------------------
// Merged prep kernel: deform-weight transpose + 4 conv-weight bf16 splits
// ---------------------------------------------------------------------------
__device__ __forceinline__ void split_one(const float* w, __nv_bfloat16* h,
                                          __nv_bfloat16* l, int idx,
                                          int Cout_real, int ocp, int Cin) {
    int c  = idx % Cin;
    int oc = (idx / Cin) % ocp;
    int k  = idx / (Cin * ocp);
    float v = (oc < Cout_real) ? w[((size_t)oc * Cin + c) * 9 + k] : 0.f;
    __nv_bfloat16 hi = __float2bfloat16(v);
    float hf = __bfloat162float(hi);
    h[idx] = hi;
    l[idx] = __float2bfloat16(v - hf);
}

constexpr int PN0 = CIN * KK * COUT;        // 73728 (wt)
constexpr int PN1 = 9 * 64 * 192;           // 110592
constexpr int PN2 = 9 * 64 * 64;            // 36864
constexpr int PN4 = 9 * OCP4 * 64;          // 258048
constexpr int PTOT = PN0 + PN1 + 2 * PN2 + PN4;  // 516096

__global__ void prep_k(const float* __restrict__ dw, float* __restrict__ wt,
                       const float* __restrict__ w1, const float* __restrict__ w2,
                       const float* __restrict__ w3, const float* __restrict__ w4) {
    int idx = blockIdx.x * blockDim.x + threadIdx.x;
    if (idx >= PTOT) return;
    if (idx < PN0) {
        int o   = idx % COUT;
        int k   = (idx / COUT) % KK;
        int cin = idx / (COUT * KK);
        wt[idx] = dw[((size_t)o * CIN + cin) * KK + k];
        return;
    }
    idx -= PN0;
    if (idx < PN1) { split_one(w1, g_w1h, g_w1l, idx, 64, 64, 192); return; }
    idx -= PN1;
    if (idx < PN2) { split_one(w2, g_w2h, g_w2l, idx, 64, 64, 64); return; }
    idx -= PN2;
    if (idx < PN2) { split_one(w3, g_w3h, g_w3l, idx, 64, 64, 64); return; }
    idx -= PN2;
    split_one(w4, g_w4h, g_w4l, idx, OC4, OCP4, 64);
}

// Convert float NCHW -> [b][y][px][Cin] bf16 hi/lo. grid (HH, BATCH), 256 thr.
__global__ void __launch_bounds__(256)
convert_k(const float* __restrict__ in, __nv_bfloat16* __restrict__ oh,
          __nv_bfloat16* __restrict__ ol, int Cin) {
    __shared__ __nv_bfloat16 sh[128][40];
    __shared__ __nv_bfloat16 sl[128][40];
    const int tid  = threadIdx.x;
    const int wid  = tid >> 5;
    const int lane = tid & 31;
    const int y = blockIdx.x;
    const int b = blockIdx.y;
    const int nct = Cin >> 5;

    for (int ct = 0; ct < nct; ct++) {
        __syncthreads();
        for (int r = 0; r < 4; r++) {
            int c = ct * 32 + r * 8 + wid;
            const float4* src = (const float4*)(in + ((size_t)b * Cin + c) * HWSZ + (size_t)y * WW);
            float4 v = src[lane];
            int px = lane * 4;
            float vv[4] = {v.x, v.y, v.z, v.w};
#pragma unroll
            for (int j = 0; j < 4; j++) {
                __nv_bfloat16 h = __float2bfloat16(vv[j]);
                float hf = __bfloat162float(h);
                sh[px + j][r * 8 + wid] = h;
                sl[px + j][r * 8 + wid] = __float2bfloat16(vv[j] - hf);
            }
        }
        __syncthreads();
        for (int i = tid; i < 512; i += 256) {
            int px = i >> 2, cc = (i & 3) * 8;
            size_t dst = ((size_t)(b * HWSZ + y * WW + px)) * Cin + ct * 32 + cc;
            *(uint4*)(oh + dst) = *(uint4*)&sh[px][cc];
            *(uint4*)(ol + dst) = *(uint4*)&sl[px][cc];
        }
    }
}

// ---------------------------------------------------------------------------
// Shared smem layout for conv kernels
// ---------------------------------------------------------------------------
constexpr int LDX = 72;
constexpr int LDW = 72;
constexpr uint32_t SX_H = 0;
constexpr uint32_t SX_L = SX_H + 130 * LDX * 2;        // 18720
constexpr uint32_t SW_H = SX_L + 130 * LDX * 2;        // 37440
constexpr uint32_t SW_L = SW_H + 3 * 64 * LDW * 2;     // 65088
constexpr uint32_t SMEMC = SW_L + 3 * 64 * LDW * 2 + 64; // 92800

// ---------------------------------------------------------------------------
// Staging helpers (128 threads)
// ---------------------------------------------------------------------------
__device__ __forceinline__ void stage_x_pre(
    char* sm, uint32_t sbase, const __nv_bfloat16* xh, const __nv_bfloat16* xl,
    int tid, int b, int y, int di, int sl, int Cin) {
    const int yy = y + di;
    const bool valid = (yy >= 0) && (yy < HH);
    if (valid) {
        const size_t rowbase = ((size_t)(b * HH + yy) * WW) * Cin + sl * 64;
        for (int i = tid; i < 1024; i += 128) {
            int px = i >> 3, cc = (i & 7) * 8;
            size_t src = rowbase + (size_t)px * Cin + cc;
            uint32_t off = (uint32_t)((1 + px) * LDX + cc) * 2;
            CP16(sbase + SX_H + off, xh + src);
            CP16(sbase + SX_L + off, xl + src);
        }
    } else {
        const uint4 z = make_uint4(0, 0, 0, 0);
        for (int i = tid; i < 1024; i += 128) {
            int px = i >> 3, cc = (i & 7) * 8;
            uint32_t off = (uint32_t)((1 + px) * LDX + cc) * 2;
            *(uint4*)(sm + SX_H + off) = z;
            *(uint4*)(sm + SX_L + off) = z;
        }
    }
}

__device__ __forceinline__ void stage_w(
    uint32_t sbase, const __nv_bfloat16* wh, const __nv_bfloat16* wl,
    int tid, int di, int oc0, int sl, int Cin, int ocp) {
    for (int i = tid; i < 3 * 512; i += 128) {
        int t = i >> 9, r = i & 511;
        int ocl = r >> 3, cc = (r & 7) * 8;
        size_t gidx = ((size_t)((di + 1) * 3 + t) * ocp + oc0 + ocl) * Cin
                    + (size_t)sl * 64 + cc;
        uint32_t doff = (uint32_t)((t * 64 + ocl) * LDW + cc) * 2;
        CP16(sbase + SW_H + doff, wh + gidx);
        CP16(sbase + SW_L + doff, wl + gidx);
    }
}

// ---------------------------------------------------------------------------
// MMA core: warp = 32 oc (2 m16 groups) x 64 px (4 nt2 x 2 tiles).
// d[2][8][4]. B fragments shared across both oc groups (halved ldsm traffic).
// ---------------------------------------------------------------------------
__device__ __forceinline__ void conv_mma_core(
    uint32_t sbase, float (*d)[8][4],
    int w_oc, int w_px, int lane) {
    const int a_rl  = (lane & 15);
    const int a_ko  = (lane >> 4) * 8;
    const int b_r   = lane & 7;
    const int b_ko  = ((lane >> 3) & 1) * 8;
    const int b_seg = lane >> 4;
#pragma unroll
    for (int djs = 0; djs < 3; djs++) {
#pragma unroll
        for (int kc = 0; kc < 4; kc++) {
            uint32_t aH[2][4], aL[2][4];
#pragma unroll
            for (int g2 = 0; g2 < 2; g2++) {
                uint32_t off = (uint32_t)((djs * 64 + w_oc * 32 + g2 * 16 + a_rl) * LDW
                                          + kc * 16 + a_ko) * 2;
                ldsm_x4(aH[g2][0], aH[g2][1], aH[g2][2], aH[g2][3], sbase + SW_H + off);
                ldsm_x4(aL[g2][0], aL[g2][1], aL[g2][2], aL[g2][3], sbase + SW_L + off);
            }
#pragma unroll
            for (int nt2 = 0; nt2 < 4; nt2++) {
                const int row = djs + w_px * 64 + nt2 * 16 + b_seg * 8 + b_r;
                uint32_t off = (uint32_t)(row * LDX + kc * 16 + b_ko) * 2;
                uint32_t bh0, bh1, bh2, bh3, bl0, bl1, bl2, bl3;
                ldsm_x4(bh0, bh1, bh2, bh3, sbase + SX_H + off);
                ldsm_x4(bl0, bl1, bl2, bl3, sbase + SX_L + off);
#pragma unroll
                for (int g2 = 0; g2 < 2; g2++) {
                    float* d0 = d[g2][nt2 * 2];
                    float* d1 = d[g2][nt2 * 2 + 1];
                    mma16816(d0, aH[g2], bh0, bh1);
                    mma16816(d0, aH[g2], bl0, bl1);
                    mma16816(d0, aL[g2], bh0, bh1);
                    mma16816(d1, aH[g2], bh2, bh3);
                    mma16816(d1, aH[g2], bl2, bl3);
                    mma16816(d1, aL[g2], bh2, bh3);
                }
            }
        }
    }
}

// ---------------------------------------------------------------------------
// conv_pair_k — pre-split pair input, pair output, lrelu. 64 oc.
// 128 threads / 4 warps: warp = (w_oc, w_px) in 2x2. grid (HH, 1, BATCH).
// ---------------------------------------------------------------------------
__global__ void __launch_bounds__(128, 2)
conv_pair_k(const __nv_bfloat16* __restrict__ xh, const __nv_bfloat16* __restrict__ xl,
            const __nv_bfloat16* __restrict__ wh, const __nv_bfloat16* __restrict__ wl,
            const float* __restrict__ bias,
            __nv_bfloat16* __restrict__ outh, __nv_bfloat16* __restrict__ outl,
            int Cin) {
    extern __shared__ char sm[];
    const uint32_t sbase = smem_u32(sm);

    const int tid  = threadIdx.x;
    const int w    = tid >> 5;
    const int lane = tid & 31;
    const int y = blockIdx.x;
    const int b = blockIdx.z;
    const int w_oc = w & 1;
    const int w_px = w >> 1;

    __nv_bfloat16* sxh = (__nv_bfloat16*)(sm + SX_H);
    __nv_bfloat16* sxl = (__nv_bfloat16*)(sm + SX_L);

    for (int i = tid; i < LDX; i += 128) {
        sxh[i] = __float2bfloat16(0.f);
        sxl[i] = __float2bfloat16(0.f);
        sxh[129 * LDX + i] = __float2bfloat16(0.f);
        sxl[129 * LDX + i] = __float2bfloat16(0.f);
    }

    float d[2][8][4];
#pragma unroll
    for (int g2 = 0; g2 < 2; g2++)
#pragma unroll
        for (int nt = 0; nt < 8; nt++)
#pragma unroll
            for (int j = 0; j < 4; j++) d[g2][nt][j] = 0.f;

    const int nslab = Cin >> 6;
    for (int sl = 0; sl < nslab; sl++) {
        for (int di = -1; di <= 1; di++) {
            __syncthreads();
            stage_x_pre(sm, sbase, xh, xl, tid, b, y, di, sl, Cin);
            stage_w(sbase, wh, wl, tid, di, 0, sl, Cin, 64);
            CP_COMMIT();
            CP_WAIT0();
            __syncthreads();
            conv_mma_core(sbase, d, w_oc, w_px, lane);
        }
    }

    // pair epilogue: bias+lrelu, split, smem transpose, coalesced store
    const int g   = lane >> 2;
    const int tig = lane & 3;
    __syncthreads();
#pragma unroll
    for (int g2 = 0; g2 < 2; g2++) {
        int ol0 = w_oc * 32 + g2 * 16 + g;
        int ol1 = ol0 + 8;
        float bv0 = bias[ol0], bv1 = bias[ol1];
#pragma unroll
        for (int nt = 0; nt < 8; nt++) {
            int px = w_px * 64 + nt * 8 + tig * 2;
#pragma unroll
            for (int j = 0; j < 4; j++) {
                int ocl = (j < 2) ? ol0 : ol1;
                float v = d[g2][nt][j] + ((j < 2) ? bv0 : bv1);
                v = (v >= 0.f) ? v : 0.1f * v;
                __nv_bfloat16 h = __float2bfloat16(v);
                float hf = __bfloat162float(h);
                int pxe = px + (j & 1);
                sxh[pxe * LDX + ocl] = h;
                sxl[pxe * LDX + ocl] = __float2bfloat16(v - hf);
            }
        }
    }
    __syncthreads();
    for (int i = tid; i < 1024; i += 128) {
        int px = i >> 3, cc = (i & 7) * 8;
        size_t dst = ((size_t)(b * HH + y) * WW + px) * 64 + cc;
        *(uint4*)(outh + dst) = *(uint4*)&sxh[px * LDX + cc];
        *(uint4*)(outl + dst) = *(uint4*)&sxl[px * LDX + cc];
    }
}

// ---------------------------------------------------------------------------
// conv_f_k — pre-split pair input, FLOAT output (+bias, no act). For conv4.
// grid (HH, ocp/64, BATCH).
// ---------------------------------------------------------------------------
__global__ void __launch_bounds__(128, 2)
conv_f_k(const __nv_bfloat16* __restrict__ xh, const __nv_bfloat16* __restrict__ xl,
         const __nv_bfloat16* __restrict__ wh, const __nv_bfloat16* __restrict__ wl,
         const float* __restrict__ bias, float* __restrict__ out,
         int Cin, int ocp, int Cout_real) {
    extern __shared__ char sm[];
    const uint32_t sbase = smem_u32(sm);

    const int tid  = threadIdx.x;
    const int w    = tid >> 5;
    const int lane = tid & 31;
    const int y = blockIdx.x;
    const int m = blockIdx.y;
    const int b = blockIdx.z;
    const int oc0  = m * 64;
    const int w_oc = w & 1;
    const int w_px = w >> 1;

    __nv_bfloat16* sxh = (__nv_bfloat16*)(sm + SX_H);
    __nv_bfloat16* sxl = (__nv_bfloat16*)(sm + SX_L);

    for (int i = tid; i < LDX; i += 128) {
        sxh[i] = __float2bfloat16(0.f);
        sxl[i] = __float2bfloat16(0.f);
        sxh[129 * LDX + i] = __float2bfloat16(0.f);
        sxl[129 * LDX + i] = __float2bfloat16(0.f);
    }

    float d[2][8][4];
#pragma unroll
    for (int g2 = 0; g2 < 2; g2++)
#pragma unroll
        for (int nt = 0; nt < 8; nt++)
#pragma unroll
            for (int j = 0; j < 4; j++) d[g2][nt][j] = 0.f;

    const int nslab = Cin >> 6;
    for (int sl = 0; sl < nslab; sl++) {
        for (int di = -1; di <= 1; di++) {
            __syncthreads();
            stage_x_pre(sm, sbase, xh, xl, tid, b, y, di, sl, Cin);
            stage_w(sbase, wh, wl, tid, di, oc0, sl, Cin, ocp);
            CP_COMMIT();
            CP_WAIT0();
            __syncthreads();
            conv_mma_core(sbase, d, w_oc, w_px, lane);
        }
    }

    const int g   = lane >> 2;
    const int tig = lane & 3;
#pragma unroll
    for (int g2 = 0; g2 < 2; g2++) {
#pragma unroll
        for (int nt = 0; nt < 8; nt++) {
            int px  = w_px * 64 + nt * 8 + tig * 2;
            int o0  = oc0 + w_oc * 32 + g2 * 16 + g;
            int o1  = o0 + 8;
            size_t rowoff = (size_t)y * WW + px;
            if (o0 < Cout_real) {
                float bv = bias[o0];
                *(float2*)(out + ((size_t)b * Cout_real + o0) * HWSZ + rowoff)
                    = make_float2(d[g2][nt][0] + bv, d[g2][nt][1] + bv);
            }
            if (o1 < Cout_real) {
                float bv = bias[o1];
                *(float2*)(out + ((size_t)b * Cout_real + o1) * HWSZ + rowoff)
                    = make_float2(d[g2][nt][2] + bv, d[g2][nt][3] + bv);
            }
        }
    }
}

// ---------------------------------------------------------------------------
// Deformable conv — R4 best version (+ fast activations, verified neutral).
// ---------------------------------------------------------------------------
__global__ void __launch_bounds__(128, 4)
deform_k(const float* __restrict__ x, const float* __restrict__ o4,
         const float* __restrict__ wt, const float* __restrict__ bias,
         float* __restrict__ out) {
    const int tx = threadIdx.x, ty = threadIdx.y;
    const int tid = ty * 32 + tx;
    const int b   = blockIdx.z;
    const int px  = blockIdx.x * 32 + tx;
    const int py  = blockIdx.y * 4 + ty;
    const int p   = py * WW + px;

    __shared__ __align__(16) u64 s_w[8 * 9 * 32];

    u64 acc[32];
#pragma unroll
    for (int q = 0; q < 32; q++) acc[q] = 0ull;

    const float* xb = x + (size_t)b * CIN * HWSZ;
    const float* ob = o4 + (size_t)b * OC4 * HWSZ;

    for (int g = 0; g < DG; g++) {
        __syncthreads();
        const u64* wg = (const u64*)(wt + (size_t)g * 8 * 9 * 64);
        for (int i = tid; i < 8 * 9 * 32; i += 128) s_w[i] = wg[i];
        __syncthreads();

        const float* xg = xb + (size_t)g * 8 * HWSZ;

        for (int k = 0; k < KK; k++) {
            float dy = 10.f * fast_tanh(ob[(size_t)(g * 18 + 2 * k) * HWSZ + p]);
            float dx = 10.f * fast_tanh(ob[(size_t)(g * 18 + 2 * k + 1) * HWSZ + p]);
            float m  = fast_sigmoid(ob[(size_t)(288 + g * 9 + k) * HWSZ + p]);

            float fy = (float)py - 1.f + (float)(k / 3) + dy;
            float fx = (float)px - 1.f + (float)(k % 3) + dx;
            float y0f = floorf(fy), x0f = floorf(fx);
            float ly = fy - y0f, lx = fx - x0f;
            int y0 = (int)y0f, x0 = (int)x0f;
            int y1 = y0 + 1, x1 = x0 + 1;

            bool vy0 = (y0 >= 0) && (y0 < HH);
            bool vy1 = (y1 >= 0) && (y1 < HH);
            bool vx0 = (x0 >= 0) && (x0 < WW);
            bool vx1 = (x1 >= 0) && (x1 < WW);

            float w00 = (1.f - ly) * (1.f - lx) * ((vy0 && vx0) ? m : 0.f);
            float w01 = (1.f - ly) * lx         * ((vy0 && vx1) ? m : 0.f);
            float w10 = ly * (1.f - lx)         * ((vy1 && vx0) ? m : 0.f);
            float w11 = ly * lx                 * ((vy1 && vx1) ? m : 0.f);

            int yc0 = min(max(y0, 0), HH - 1);
            int yc1 = min(max(y1, 0), HH - 1);
            int xc0 = min(max(x0, 0), WW - 1);
            int xc1 = min(max(x1, 0), WW - 1);
            int i00 = yc0 * WW + xc0, i01 = yc0 * WW + xc1;
            int i10 = yc1 * WW + xc0, i11 = yc1 * WW + xc1;

#pragma unroll
            for (int c = 0; c < 8; c++) {
                const float* xc = xg + (size_t)c * HWSZ;
                float v = w00 * xc[i00] + w01 * xc[i01] + w10 * xc[i10] + w11 * xc[i11];
                u64 v2 = pk2(v, v);
                const ulonglong2* wp = (const ulonglong2*)&s_w[(c * 9 + k) * 32];
#pragma unroll
                for (int q = 0; q < 16; q++) {
                    ulonglong2 wq = wp[q];
                    acc[q * 2 + 0] = ffma2(v2, wq.x, acc[q * 2 + 0]);
                    acc[q * 2 + 1] = ffma2(v2, wq.y, acc[q * 2 + 1]);
                }
            }
        }
    }

    float* outb = out + (size_t)b * COUT * HWSZ + p;
#pragma unroll
    for (int q = 0; q < 32; q++) {
        float2 v = upk(acc[q]);
        outb[(size_t)(2 * q + 0) * HWSZ] = v.x + bias[2 * q + 0];
        outb[(size_t)(2 * q + 1) * HWSZ] = v.y + bias[2 * q + 1];
    }
}

// ---------------------------------------------------------------------------
// Launcher (conv4 stays at launch slot 6 for the ncu -s 5 capture)
// ---------------------------------------------------------------------------
extern "C" void kernel_launch(void* const* d_in, const int* in_sizes, int n_in,
                              void* d_out, int out_size) {
    const float* x          = (const float*)d_in[0];
    const float* extra_feat = (const float*)d_in[1];
    const float* w1 = (const float*)d_in[2];
    const float* b1 = (const float*)d_in[3];
    const float* w2 = (const float*)d_in[4];
    const float* b2 = (const float*)d_in[5];
    const float* w3 = (const float*)d_in[6];
    const float* b3 = (const float*)d_in[7];
    const float* w4 = (const float*)d_in[8];
    const float* b4 = (const float*)d_in[9];
    const float* weight = (const float*)d_in[10];
    const float* bias   = (const float*)d_in[11];
    float* out = (float*)d_out;

    float *o4, *wt;
    __nv_bfloat16 *axh, *axl, *p1h, *p1l, *p2h, *p2l;
    __nv_bfloat16 *w1h, *w1l, *w2h, *w2l, *w3h, *w3l, *w4h, *w4l;
    cudaGetSymbolAddress((void**)&o4, g_o4);
    cudaGetSymbolAddress((void**)&wt, g_wt);
    cudaGetSymbolAddress((void**)&axh, g_axh);
    cudaGetSymbolAddress((void**)&axl, g_axl);
    cudaGetSymbolAddress((void**)&p1h, g_p1h);
    cudaGetSymbolAddress((void**)&p1l, g_p1l);
    cudaGetSymbolAddress((void**)&p2h, g_p2h);
    cudaGetSymbolAddress((void**)&p2l, g_p2l);
    cudaGetSymbolAddress((void**)&w1h, g_w1h);
    cudaGetSymbolAddress((void**)&w1l, g_w1l);
    cudaGetSymbolAddress((void**)&w2h, g_w2h);
    cudaGetSymbolAddress((void**)&w2l, g_w2l);
    cudaGetSymbolAddress((void**)&w3h, g_w3h);
    cudaGetSymbolAddress((void**)&w3l, g_w3l);
    cudaGetSymbolAddress((void**)&w4h, g_w4h);
    cudaGetSymbolAddress((void**)&w4l, g_w4l);

    cudaFuncSetAttribute(conv_pair_k, cudaFuncAttributeMaxDynamicSharedMemorySize, SMEMC);
    cudaFuncSetAttribute(conv_f_k, cudaFuncAttributeMaxDynamicSharedMemorySize, SMEMC);

    // 1: merged prep
    prep_k<<<(PTOT + 255) / 256, 256>>>(weight, wt, w1, w2, w3, w4);
    // 2: extra_feat -> pre-split pair
    convert_k<<<dim3(HH, BATCH), 256>>>(extra_feat, axh, axl, 192);
    // 3: conv1: ax (192ch) -> p1 pair, lrelu
    conv_pair_k<<<dim3(HH, 1, BATCH), 128, SMEMC>>>(axh, axl, w1h, w1l, b1, p1h, p1l, 192);
    // 4: conv2: p1 -> p2, lrelu
    conv_pair_k<<<dim3(HH, 1, BATCH), 128, SMEMC>>>(p1h, p1l, w2h, w2l, b2, p2h, p2l, 64);
    // 5: conv3: p2 -> p1, lrelu
    conv_pair_k<<<dim3(HH, 1, BATCH), 128, SMEMC>>>(p2h, p2l, w3h, w3l, b3, p1h, p1l, 64);
    // 6: conv4: p1 -> o4 (432ch float, +bias)  [ncu capture target]
    conv_f_k<<<dim3(HH, OCP4 / 64, BATCH), 128, SMEMC>>>(p1h, p1l, w4h, w4l, b4, o4,
                                                         64, OCP4, OC4);
    // 7: deformable conv: x + o4 -> out
    deform_k<<<dim3(WW / 32, HH / 4, BATCH), dim3(32, 4)>>>(x, o4, wt, bias, out);
}